// round 2
// baseline (speedup 1.0000x reference)
#include <cuda_runtime.h>

#define NB    2
#define NTOK  1024
#define DM    768
#define NH    12
#define DH    64
#define BHH   (NB*NH)
#define NN    (NTOK*NTOK)
#define QK_SCALE 0.125f

// ---------------- scratch (static device memory; no allocations) ----------------
__device__ float g_xn[NB*NTOK*DM];
__device__ float g_q[BHH*NTOK*DH];
__device__ float g_k[BHH*NTOK*DH];
__device__ float g_v[BHH*NTOK*DH];
__device__ float g_o[BHH*NTOK*DH];
__device__ float g_rsinv[BHH*NTOK];
__device__ float g_M[NH*NH];
__device__ float g_attn[(size_t)BHH*NN];   // ~100.7 MB

// ---------------- K1: LayerNorm ----------------
__global__ void ln_kernel(const float* __restrict__ x,
                          const float* __restrict__ gamma,
                          const float* __restrict__ beta) {
    int row = blockIdx.x;
    const float* xr = x + (size_t)row * DM;
    int t = threadIdx.x;
    float v[3];
    float s = 0.f, ss = 0.f;
#pragma unroll
    for (int i = 0; i < 3; i++) {
        v[i] = xr[t + i*256];
        s += v[i]; ss += v[i]*v[i];
    }
#pragma unroll
    for (int o = 16; o > 0; o >>= 1) {
        s  += __shfl_xor_sync(0xffffffffu, s,  o);
        ss += __shfl_xor_sync(0xffffffffu, ss, o);
    }
    __shared__ float sm1[8], sm2[8];
    int lane = t & 31, w = t >> 5;
    if (lane == 0) { sm1[w] = s; sm2[w] = ss; }
    __syncthreads();
    if (t == 0) {
        float a = 0.f, b = 0.f;
#pragma unroll
        for (int i = 0; i < 8; i++) { a += sm1[i]; b += sm2[i]; }
        sm1[0] = a; sm2[0] = b;
    }
    __syncthreads();
    float mean = sm1[0] * (1.f/DM);
    float var  = sm2[0] * (1.f/DM) - mean*mean;
    float inv  = rsqrtf(var + 1e-5f);
    float* outr = g_xn + (size_t)row * DM;
#pragma unroll
    for (int i = 0; i < 3; i++) {
        int c = t + i*256;
        outr[c] = (v[i]-mean)*inv*gamma[c] + beta[c];
    }
}

// ---------------- K2: QKV GEMM  C[2048,2304] = xn @ w_qkv^T, scatter to Q/K/V ----------------
__global__ void qkv_gemm_kernel(const float* __restrict__ wqkv) {
    __shared__ __align__(16) float As[64][20];  // [row i][k]  (broadcast side, padded)
    __shared__ __align__(16) float Ws[16][68];  // [k][col j]  (transposed)
    int t = threadIdx.x;
    int ty = t >> 4, tx = t & 15;
    int i0 = blockIdx.y * 64, j0 = blockIdx.x * 64;
    int rl = t >> 2, kq = t & 3;
    const float* Abase = g_xn + (size_t)(i0 + rl) * DM + kq*4;
    const float* Wbase = wqkv + (size_t)(j0 + rl) * DM + kq*4;
    float acc[4][4] = {};
    for (int k0 = 0; k0 < DM; k0 += 16) {
        float4 a  = *(const float4*)(Abase + k0);
        float4 wv = *(const float4*)(Wbase + k0);
        __syncthreads();
        *(float4*)&As[rl][kq*4] = a;
        Ws[kq*4+0][rl] = wv.x; Ws[kq*4+1][rl] = wv.y;
        Ws[kq*4+2][rl] = wv.z; Ws[kq*4+3][rl] = wv.w;
        __syncthreads();
#pragma unroll
        for (int k4 = 0; k4 < 16; k4 += 4) {
            float4 am[4];
#pragma unroll
            for (int i = 0; i < 4; i++) am[i] = *(const float4*)&As[ty*4+i][k4];
#pragma unroll
            for (int kk = 0; kk < 4; kk++) {
                float4 bv = *(const float4*)&Ws[k4+kk][tx*4];
                float ai[4];
                ai[0] = kk==0?am[0].x:kk==1?am[0].y:kk==2?am[0].z:am[0].w;
                ai[1] = kk==0?am[1].x:kk==1?am[1].y:kk==2?am[1].z:am[1].w;
                ai[2] = kk==0?am[2].x:kk==1?am[2].y:kk==2?am[2].z:am[2].w;
                ai[3] = kk==0?am[3].x:kk==1?am[3].y:kk==2?am[3].z:am[3].w;
#pragma unroll
                for (int i = 0; i < 4; i++) {
                    acc[i][0] += ai[i]*bv.x; acc[i][1] += ai[i]*bv.y;
                    acc[i][2] += ai[i]*bv.z; acc[i][3] += ai[i]*bv.w;
                }
            }
        }
    }
#pragma unroll
    for (int i = 0; i < 4; i++) {
#pragma unroll
        for (int j = 0; j < 4; j++) {
            int gi = i0 + ty*4 + i;
            int gj = j0 + tx*4 + j;
            int b = gi >> 10, n = gi & 1023;
            int which = gj / DM;
            int r = gj - which*DM;
            int h = r >> 6, d = r & 63;
            float* dst = (which == 0) ? g_q : (which == 1 ? g_k : g_v);
            dst[(((size_t)b*NH + h)*NTOK + n)*DH + d] = acc[i][j];
        }
    }
}

// ---------------- K3: S = QK^T*scale, E = exp(S), row sums (per bh, 64-n tile) ----------------
__global__ void attn_kernel() {
    __shared__ __align__(16) float Qt[64][68];  // [d][n-local] (transposed once)
    __shared__ __align__(16) float Ks[64][68];  // [m-local][d]; reused as E-stage (stride 67)
    __shared__ float ssum[64];
    int t = threadIdx.x;
    int ty = t >> 4, tx = t & 15;
    int lane = t & 31, w = t >> 5;
    int bh = blockIdx.y;
    int n0 = blockIdx.x * 64;
    size_t qb = (size_t)bh * NTOK * DH;
    size_t ab = (size_t)bh * NN;

    // load+transpose Q tile (64 n x 64 d)
#pragma unroll
    for (int r = 0; r < 4; r++) {
        int lin = r*256 + t;
        int nl = lin >> 4, dq = lin & 15;
        float4 q4 = *(const float4*)(g_q + qb + (size_t)(n0+nl)*DH + dq*4);
        Qt[dq*4+0][nl] = q4.x; Qt[dq*4+1][nl] = q4.y;
        Qt[dq*4+2][nl] = q4.z; Qt[dq*4+3][nl] = q4.w;
    }
    if (t < 64) ssum[t] = 0.f;
    float rs[4] = {0.f, 0.f, 0.f, 0.f};

    for (int m0 = 0; m0 < NTOK; m0 += 64) {
        __syncthreads();                       // Qt ready / E-stage consumed
#pragma unroll
        for (int r = 0; r < 4; r++) {
            int lin = r*256 + t;
            int ml = lin >> 4, dq = lin & 15;
            *(float4*)&Ks[ml][dq*4] =
                *(const float4*)(g_k + qb + (size_t)(m0+ml)*DH + dq*4);
        }
        __syncthreads();
        float acc[4][4] = {};
#pragma unroll
        for (int k4 = 0; k4 < 64; k4 += 4) {
            float4 am[4];
#pragma unroll
            for (int i = 0; i < 4; i++) am[i] = *(const float4*)&Ks[ty*4+i][k4];
#pragma unroll
            for (int kk = 0; kk < 4; kk++) {
                float4 bv = *(const float4*)&Qt[k4+kk][tx*4];
                float ai[4];
                ai[0] = kk==0?am[0].x:kk==1?am[0].y:kk==2?am[0].z:am[0].w;
                ai[1] = kk==0?am[1].x:kk==1?am[1].y:kk==2?am[1].z:am[1].w;
                ai[2] = kk==0?am[2].x:kk==1?am[2].y:kk==2?am[2].z:am[2].w;
                ai[3] = kk==0?am[3].x:kk==1?am[3].y:kk==2?am[3].z:am[3].w;
#pragma unroll
                for (int i = 0; i < 4; i++) {
                    acc[i][0] += ai[i]*bv.x; acc[i][1] += ai[i]*bv.y;
                    acc[i][2] += ai[i]*bv.z; acc[i][3] += ai[i]*bv.w;
                }
            }
        }
        __syncthreads();                       // done reading Ks -> reuse as E stage
        float* Es = &Ks[0][0];                 // logical stride 67
#pragma unroll
        for (int i = 0; i < 4; i++)
#pragma unroll
            for (int j = 0; j < 4; j++) {
                float e = __expf(acc[i][j] * QK_SCALE);
                Es[(ty*4+i)*67 + (tx*4+j)] = e;   // [m-local][n-local]
                rs[j] += e;
            }
        __syncthreads();
        // coalesced transpose-out: warp w writes n rows w*8..w*8+7, m contiguous
#pragma unroll
        for (int rr = 0; rr < 8; rr++) {
            int nl = w*8 + rr;
            float v0 = Es[lane*67 + nl];
            float v1 = Es[(lane+32)*67 + nl];
            float* dst = g_attn + ab + (size_t)(n0+nl)*NTOK + m0;
            dst[lane]    = v0;
            dst[lane+32] = v1;
        }
    }
    __syncthreads();
#pragma unroll
    for (int j = 0; j < 4; j++) atomicAdd(&ssum[tx*4+j], rs[j]);
    __syncthreads();
    if (t < 64) g_rsinv[bh*NTOK + n0 + t] = 1.0f / ssum[t];
}

// ---------------- K4: M = (-0.5*theta) @ gnn_w  (12x12) ----------------
__global__ void mcompute_kernel(const float* __restrict__ theta,
                                const float* __restrict__ gw) {
    int idx = threadIdx.x;
    if (idx < NH*NH) {
        int i = idx / NH, k = idx - i*NH;
        float s = 0.f;
#pragma unroll
        for (int j = 0; j < NH; j++) s += theta[i*NH+j] * gw[j*NH+k];
        g_M[idx] = -0.5f * s;
    }
}

// ---------------- K5: in-place P = softmax(attn) + relu(M @ softmax(attn)) ----------------
__global__ void pmix_kernel() {
    __shared__ float Ms[NH*NH];
    if (threadIdx.x < NH*NH) Ms[threadIdx.x] = g_M[threadIdx.x];
    __syncthreads();
    size_t pos = (size_t)blockIdx.x * 256 + threadIdx.x;   // < 2*1024*1024
    int b  = (int)(pos >> 20);
    int nm = (int)(pos & (size_t)(NN - 1));
    int n  = nm >> 10;
    size_t base = (size_t)b * NH * NN + nm;
    float a[NH];
#pragma unroll
    for (int h = 0; h < NH; h++) {
        float inv = g_rsinv[(b*NH + h)*NTOK + n];
        a[h] = g_attn[base + (size_t)h*NN] * inv;
    }
#pragma unroll
    for (int i = 0; i < NH; i++) {
        float s = 0.f;
#pragma unroll
        for (int k = 0; k < NH; k++) s += Ms[i*NH+k] * a[k];
        g_attn[base + (size_t)i*NN] = a[i] + fmaxf(s, 0.f);
    }
}

// ---------------- K6: O = P @ V per (b,h)  (64n x 64d tiles, k=m chunks of 16) ----------------
__global__ void pv_kernel() {
    __shared__ __align__(16) float Ps[64][20];  // [n-local][m-chunk]
    __shared__ __align__(16) float Vs[16][64];  // [m-chunk][d]
    int t = threadIdx.x;
    int ty = t >> 4, tx = t & 15;
    int bh = blockIdx.y;
    int n0 = blockIdx.x * 64;
    size_t ab = (size_t)bh * NN;
    size_t vb = (size_t)bh * NTOK * DH;
    int nl = t >> 2, mq = t & 3;
    int ml = t >> 4, dq = t & 15;
    float acc[4][4] = {};
    for (int m0 = 0; m0 < NTOK; m0 += 16) {
        float4 p4 = *(const float4*)(g_attn + ab + (size_t)(n0+nl)*NTOK + m0 + mq*4);
        float4 v4 = *(const float4*)(g_v + vb + (size_t)(m0+ml)*DH + dq*4);
        __syncthreads();
        *(float4*)&Ps[nl][mq*4] = p4;
        *(float4*)&Vs[ml][dq*4] = v4;
        __syncthreads();
#pragma unroll
        for (int k4 = 0; k4 < 16; k4 += 4) {
            float4 am[4];
#pragma unroll
            for (int i = 0; i < 4; i++) am[i] = *(const float4*)&Ps[ty*4+i][k4];
#pragma unroll
            for (int kk = 0; kk < 4; kk++) {
                float4 bv = *(const float4*)&Vs[k4+kk][tx*4];
                float ai[4];
                ai[0] = kk==0?am[0].x:kk==1?am[0].y:kk==2?am[0].z:am[0].w;
                ai[1] = kk==0?am[1].x:kk==1?am[1].y:kk==2?am[1].z:am[1].w;
                ai[2] = kk==0?am[2].x:kk==1?am[2].y:kk==2?am[2].z:am[2].w;
                ai[3] = kk==0?am[3].x:kk==1?am[3].y:kk==2?am[3].z:am[3].w;
#pragma unroll
                for (int i = 0; i < 4; i++) {
                    acc[i][0] += ai[i]*bv.x; acc[i][1] += ai[i]*bv.y;
                    acc[i][2] += ai[i]*bv.z; acc[i][3] += ai[i]*bv.w;
                }
            }
        }
    }
#pragma unroll
    for (int i = 0; i < 4; i++)
#pragma unroll
        for (int j = 0; j < 4; j++)
            g_o[vb + (size_t)(n0+ty*4+i)*DH + tx*4+j] = acc[i][j];
}

// ---------------- K7: Y = gather(O) @ w_out^T + b_out ----------------
__global__ void oproj_kernel(const float* __restrict__ wout,
                             const float* __restrict__ bout,
                             float* __restrict__ out) {
    __shared__ __align__(16) float As[64][20];  // [row i][k]
    __shared__ __align__(16) float Ws[16][68];  // [k][col o]
    int t = threadIdx.x;
    int ty = t >> 4, tx = t & 15;
    int i0 = blockIdx.y * 64, o0 = blockIdx.x * 64;
    int rl = t >> 2, kq = t & 3;
    float acc[4][4] = {};
    int gi = i0 + rl;
    int b = gi >> 10, n = gi & 1023;
    for (int k0 = 0; k0 < DM; k0 += 16) {
        int h = k0 >> 6;
        int d = (k0 & 63) + kq*4;
        float4 a  = *(const float4*)(g_o + (((size_t)b*NH + h)*NTOK + n)*DH + d);
        float4 wv = *(const float4*)(wout + (size_t)(o0 + rl)*DM + k0 + kq*4);
        __syncthreads();
        *(float4*)&As[rl][kq*4] = a;
        Ws[kq*4+0][rl] = wv.x; Ws[kq*4+1][rl] = wv.y;
        Ws[kq*4+2][rl] = wv.z; Ws[kq*4+3][rl] = wv.w;
        __syncthreads();
#pragma unroll
        for (int k4 = 0; k4 < 16; k4 += 4) {
            float4 am[4];
#pragma unroll
            for (int i = 0; i < 4; i++) am[i] = *(const float4*)&As[ty*4+i][k4];
#pragma unroll
            for (int kk = 0; kk < 4; kk++) {
                float4 bv = *(const float4*)&Ws[k4+kk][tx*4];
                float ai[4];
                ai[0] = kk==0?am[0].x:kk==1?am[0].y:kk==2?am[0].z:am[0].w;
                ai[1] = kk==0?am[1].x:kk==1?am[1].y:kk==2?am[1].z:am[1].w;
                ai[2] = kk==0?am[2].x:kk==1?am[2].y:kk==2?am[2].z:am[2].w;
                ai[3] = kk==0?am[3].x:kk==1?am[3].y:kk==2?am[3].z:am[3].w;
#pragma unroll
                for (int i = 0; i < 4; i++) {
                    acc[i][0] += ai[i]*bv.x; acc[i][1] += ai[i]*bv.y;
                    acc[i][2] += ai[i]*bv.z; acc[i][3] += ai[i]*bv.w;
                }
            }
        }
    }
#pragma unroll
    for (int i = 0; i < 4; i++)
#pragma unroll
        for (int j = 0; j < 4; j++) {
            int o = o0 + tx*4 + j;
            out[(size_t)(i0 + ty*4 + i)*DM + o] = acc[i][j] + bout[o];
        }
}

// ---------------- launch ----------------
extern "C" void kernel_launch(void* const* d_in, const int* in_sizes, int n_in,
                              void* d_out, int out_size) {
    const float* x      = (const float*)d_in[0];
    const float* ln_g   = (const float*)d_in[1];
    const float* ln_b   = (const float*)d_in[2];
    const float* w_qkv  = (const float*)d_in[3];
    const float* w_out  = (const float*)d_in[4];
    const float* b_out  = (const float*)d_in[5];
    const float* theta  = (const float*)d_in[6];
    const float* gnn_w  = (const float*)d_in[7];
    float* out = (float*)d_out;

    ln_kernel<<<NB*NTOK, 256>>>(x, ln_g, ln_b);
    qkv_gemm_kernel<<<dim3(36, 32), 256>>>(w_qkv);
    mcompute_kernel<<<1, 160>>>(theta, gnn_w);
    attn_kernel<<<dim3(NTOK/64, BHH), 256>>>();
    pmix_kernel<<<(NB*NN)/256, 256>>>();
    pv_kernel<<<dim3(NTOK/64, BHH), 256>>>();
    oproj_kernel<<<dim3(DM/64, NB*NTOK/64), 256>>>(w_out, b_out, out);
}

// round 5
// speedup vs baseline: 2.0674x; 2.0674x over previous
#include <cuda_runtime.h>

#define NB    2
#define NTOK  1024
#define DM    768
#define NH    12
#define DH    64
#define BHH   (NB*NH)
#define NN    (NTOK*NTOK)
#define QK_SCALE 0.125f

// ---------------- scratch (static device memory; no allocations) ----------------
__device__ float g_xn[NB*NTOK*DM];
__device__ float g_q[BHH*NTOK*DH];
__device__ float g_k[BHH*NTOK*DH];
__device__ float g_v[BHH*NTOK*DH];
__device__ float g_o[BHH*NTOK*DH];
__device__ float g_rsinv[BHH*NTOK];
__device__ float g_M[NH*NH];
__device__ float g_attn[(size_t)BHH*NN];   // ~100.7 MB

// ---------------- tf32 helpers ----------------
__device__ __forceinline__ float f2t(float x) {
    unsigned u;
    asm("cvt.rna.tf32.f32 %0, %1;" : "=r"(u) : "f"(x));
    return __uint_as_float(u);
}
__device__ __forceinline__ unsigned fb(float x) { return __float_as_uint(x); }

__device__ __forceinline__ void mma_tf32(float c[4], const unsigned a[4], const unsigned b[2]) {
    asm volatile(
        "mma.sync.aligned.m16n8k8.row.col.f32.tf32.tf32.f32 "
        "{%0,%1,%2,%3}, {%4,%5,%6,%7}, {%8,%9}, {%0,%1,%2,%3};\n"
        : "+f"(c[0]), "+f"(c[1]), "+f"(c[2]), "+f"(c[3])
        : "r"(a[0]), "r"(a[1]), "r"(a[2]), "r"(a[3]), "r"(b[0]), "r"(b[1]));
}

// ---------------- K1: LayerNorm (proven) ----------------
__global__ void ln_kernel(const float* __restrict__ x,
                          const float* __restrict__ gamma,
                          const float* __restrict__ beta) {
    int row = blockIdx.x;
    const float* xr = x + (size_t)row * DM;
    int t = threadIdx.x;
    float v[3];
    float s = 0.f, ss = 0.f;
#pragma unroll
    for (int i = 0; i < 3; i++) {
        v[i] = xr[t + i*256];
        s += v[i]; ss += v[i]*v[i];
    }
#pragma unroll
    for (int o = 16; o > 0; o >>= 1) {
        s  += __shfl_xor_sync(0xffffffffu, s,  o);
        ss += __shfl_xor_sync(0xffffffffu, ss, o);
    }
    __shared__ float sm1[8], sm2[8];
    int lane = t & 31, w = t >> 5;
    if (lane == 0) { sm1[w] = s; sm2[w] = ss; }
    __syncthreads();
    if (t == 0) {
        float a = 0.f, b = 0.f;
#pragma unroll
        for (int i = 0; i < 8; i++) { a += sm1[i]; b += sm2[i]; }
        sm1[0] = a; sm2[0] = b;
    }
    __syncthreads();
    float mean = sm1[0] * (1.f/DM);
    float var  = sm2[0] * (1.f/DM) - mean*mean;
    float inv  = rsqrtf(var + 1e-5f);
    float* outr = g_xn + (size_t)row * DM;
#pragma unroll
    for (int i = 0; i < 3; i++) {
        int c = t + i*256;
        outr[c] = (v[i]-mean)*inv*gamma[c] + beta[c];
    }
}

// ---------------- K2: QKV GEMM (tf32 mma)  C[2048,2304] = xn @ w_qkv^T ----------------
// grid (36, 16): block tile 128 rows x 64 cols. 256 thr = 8 warps (4x2), warp 32x32.
__device__ __forceinline__ void qkv_store(int gi, int gj, float v) {
    int b = gi >> 10, n = gi & 1023;
    int which = gj / DM;
    int r = gj - which*DM;
    int h = r >> 6, d = r & 63;
    float* dst = (which == 0) ? g_q : (which == 1 ? g_k : g_v);
    dst[(((size_t)b*NH + h)*NTOK + n)*DH + d] = v;
}

__global__ void qkv_mma_kernel(const float* __restrict__ wqkv) {
    __shared__ float As[128][36];
    __shared__ float Bs[64][36];
    int t = threadIdx.x;
    int lane = t & 31, wid = t >> 5;
    int wr = wid >> 1, wc = wid & 1;
    int gid = lane >> 2, tig = lane & 3;
    int i0 = blockIdx.y * 128, j0 = blockIdx.x * 64;
    int ar = t >> 3, ac4 = t & 7;
    float acc[2][4][4] = {};
    for (int k0 = 0; k0 < DM; k0 += 32) {
        float4 av[4], bv[2];
#pragma unroll
        for (int i = 0; i < 4; i++)
            av[i] = *(const float4*)(g_xn + (size_t)(i0 + ar + i*32)*DM + k0 + ac4*4);
#pragma unroll
        for (int i = 0; i < 2; i++)
            bv[i] = *(const float4*)(wqkv + (size_t)(j0 + ar + i*32)*DM + k0 + ac4*4);
        __syncthreads();
#pragma unroll
        for (int i = 0; i < 4; i++) {
            float* p = &As[ar + i*32][ac4*4];
            p[0]=f2t(av[i].x); p[1]=f2t(av[i].y); p[2]=f2t(av[i].z); p[3]=f2t(av[i].w);
        }
#pragma unroll
        for (int i = 0; i < 2; i++) {
            float* p = &Bs[ar + i*32][ac4*4];
            p[0]=f2t(bv[i].x); p[1]=f2t(bv[i].y); p[2]=f2t(bv[i].z); p[3]=f2t(bv[i].w);
        }
        __syncthreads();
#pragma unroll
        for (int ks = 0; ks < 4; ks++) {
            int kk = ks*8;
            unsigned a[2][4], b[4][2];
#pragma unroll
            for (int mi = 0; mi < 2; mi++) {
                int r = wr*32 + mi*16 + gid;
                a[mi][0] = fb(As[r][kk+tig]);     a[mi][1] = fb(As[r+8][kk+tig]);
                a[mi][2] = fb(As[r][kk+tig+4]);   a[mi][3] = fb(As[r+8][kk+tig+4]);
            }
#pragma unroll
            for (int nj = 0; nj < 4; nj++) {
                int cb = wc*32 + nj*8 + gid;
                b[nj][0] = fb(Bs[cb][kk+tig]);    b[nj][1] = fb(Bs[cb][kk+tig+4]);
            }
#pragma unroll
            for (int mi = 0; mi < 2; mi++)
#pragma unroll
                for (int nj = 0; nj < 4; nj++)
                    mma_tf32(acc[mi][nj], a[mi], b[nj]);
        }
    }
#pragma unroll
    for (int mi = 0; mi < 2; mi++)
#pragma unroll
        for (int nj = 0; nj < 4; nj++) {
            int gi = i0 + wr*32 + mi*16 + gid;
            int gj = j0 + wc*32 + nj*8 + 2*tig;
            qkv_store(gi,     gj,     acc[mi][nj][0]);
            qkv_store(gi,     gj + 1, acc[mi][nj][1]);
            qkv_store(gi + 8, gj,     acc[mi][nj][2]);
            qkv_store(gi + 8, gj + 1, acc[mi][nj][3]);
        }
}

// ---------------- K3: attn (tf32 mma) E = exp(scale*Q K^T), rowsums ----------------
// grid (NTOK/64, BHH), 128 thr = 4 warps (2x2), warp tile 32x32, m-loop of 64.
__global__ void attn_mma_kernel() {
    __shared__ float Qs[64][68];   // reused as E staging after Q-frag hoist
    __shared__ float Ks[64][68];
    __shared__ float ssum[64];
    int t = threadIdx.x;
    int lane = t & 31, wid = t >> 5;
    int wr = wid >> 1, wc = wid & 1;
    int gid = lane >> 2, tig = lane & 3;
    int bh = blockIdx.y;
    int n0 = blockIdx.x * 64;
    size_t qb = (size_t)bh * NTOK * DH;
    size_t ab = (size_t)bh * NN;

#pragma unroll
    for (int i = 0; i < 8; i++) {
        int idx = i*128 + t;
        int r = idx >> 4, c4 = idx & 15;
        float4 q4 = *(const float4*)(g_q + qb + (size_t)(n0+r)*DH + c4*4);
        float* p = &Qs[r][c4*4];
        p[0]=f2t(q4.x); p[1]=f2t(q4.y); p[2]=f2t(q4.z); p[3]=f2t(q4.w);
    }
    if (t < 64) ssum[t] = 0.f;
    __syncthreads();

    unsigned qf[2][8][4];
#pragma unroll
    for (int mi = 0; mi < 2; mi++) {
        int r = wr*32 + mi*16 + gid;
#pragma unroll
        for (int ks = 0; ks < 8; ks++) {
            int kk = ks*8;
            qf[mi][ks][0] = fb(Qs[r][kk+tig]);     qf[mi][ks][1] = fb(Qs[r+8][kk+tig]);
            qf[mi][ks][2] = fb(Qs[r][kk+tig+4]);   qf[mi][ks][3] = fb(Qs[r+8][kk+tig+4]);
        }
    }
    float rs[2][2] = {};

    for (int m0 = 0; m0 < NTOK; m0 += 64) {
        float4 kv[8];
#pragma unroll
        for (int i = 0; i < 8; i++) {
            int idx = i*128 + t;
            int r = idx >> 4, c4 = idx & 15;
            kv[i] = *(const float4*)(g_k + qb + (size_t)(m0+r)*DH + c4*4);
        }
        __syncthreads();   // prior E write-out done; prior Ks reads done
#pragma unroll
        for (int i = 0; i < 8; i++) {
            int idx = i*128 + t;
            int r = idx >> 4, c4 = idx & 15;
            float* p = &Ks[r][c4*4];
            p[0]=f2t(kv[i].x); p[1]=f2t(kv[i].y); p[2]=f2t(kv[i].z); p[3]=f2t(kv[i].w);
        }
        __syncthreads();
        float acc[2][4][4] = {};
#pragma unroll
        for (int ks = 0; ks < 8; ks++) {
            int kk = ks*8;
            unsigned b[4][2];
#pragma unroll
            for (int nj = 0; nj < 4; nj++) {
                int cb = wc*32 + nj*8 + gid;
                b[nj][0] = fb(Ks[cb][kk+tig]);  b[nj][1] = fb(Ks[cb][kk+tig+4]);
            }
#pragma unroll
            for (int mi = 0; mi < 2; mi++)
#pragma unroll
                for (int nj = 0; nj < 4; nj++)
                    mma_tf32(acc[mi][nj], qf[mi][ks], b[nj]);
        }
        // exp + rowsum + stage into Qs as E[n-local][m-local]
#pragma unroll
        for (int mi = 0; mi < 2; mi++) {
            int r = wr*32 + mi*16 + gid;
#pragma unroll
            for (int nj = 0; nj < 4; nj++) {
                int c = wc*32 + nj*8 + 2*tig;
                float e0 = __expf(acc[mi][nj][0]*QK_SCALE);
                float e1 = __expf(acc[mi][nj][1]*QK_SCALE);
                float e2 = __expf(acc[mi][nj][2]*QK_SCALE);
                float e3 = __expf(acc[mi][nj][3]*QK_SCALE);
                Qs[r][c] = e0;   Qs[r][c+1] = e1;
                Qs[r+8][c] = e2; Qs[r+8][c+1] = e3;
                rs[mi][0] += e0 + e1;
                rs[mi][1] += e2 + e3;
            }
        }
        __syncthreads();
        // coalesced write-out: warp wid handles rows wid*16..+15
#pragma unroll
        for (int rr = 0; rr < 16; rr++) {
            int row = wid*16 + rr;
            float v0 = Qs[row][lane];
            float v1 = Qs[row][lane+32];
            float* dstp = g_attn + ab + (size_t)(n0+row)*NTOK + m0;
            dstp[lane]    = v0;
            dstp[lane+32] = v1;
        }
    }
    __syncthreads();
#pragma unroll
    for (int mi = 0; mi < 2; mi++) {
        int r = wr*32 + mi*16 + gid;
        atomicAdd(&ssum[r],   rs[mi][0]);
        atomicAdd(&ssum[r+8], rs[mi][1]);
    }
    __syncthreads();
    if (t < 64) g_rsinv[bh*NTOK + n0 + t] = 1.0f / ssum[t];
}

// ---------------- K4: M = (-0.5*theta) @ gnn_w ----------------
__global__ void mcompute_kernel(const float* __restrict__ theta,
                                const float* __restrict__ gw) {
    int idx = threadIdx.x;
    if (idx < NH*NH) {
        int i = idx / NH, k = idx - i*NH;
        float s = 0.f;
#pragma unroll
        for (int j = 0; j < NH; j++) s += theta[i*NH+j] * gw[j*NH+k];
        g_M[idx] = -0.5f * s;
    }
}

// ---------------- K5: in-place P = a + relu(M @ a) (proven) ----------------
__global__ void pmix_kernel() {
    __shared__ float Ms[NH*NH];
    if (threadIdx.x < NH*NH) Ms[threadIdx.x] = g_M[threadIdx.x];
    __syncthreads();
    size_t pos = (size_t)blockIdx.x * 256 + threadIdx.x;
    int b  = (int)(pos >> 20);
    int nm = (int)(pos & (size_t)(NN - 1));
    int n  = nm >> 10;
    size_t base = (size_t)b * NH * NN + nm;
    float a[NH];
#pragma unroll
    for (int h = 0; h < NH; h++) {
        float inv = g_rsinv[(b*NH + h)*NTOK + n];
        a[h] = g_attn[base + (size_t)h*NN] * inv;
    }
#pragma unroll
    for (int i = 0; i < NH; i++) {
        float s = 0.f;
#pragma unroll
        for (int k = 0; k < NH; k++) s += Ms[i*NH+k] * a[k];
        g_attn[base + (size_t)i*NN] = a[i] + fmaxf(s, 0.f);
    }
}

// ---------------- K6: O = P @ V per bh (tf32 mma), grid (NTOK/128, BHH) ----------------
__global__ void pv_mma_kernel() {
    __shared__ float Ps[128][36];
    __shared__ float Vs[32][68];
    int t = threadIdx.x;
    int lane = t & 31, wid = t >> 5;
    int wr = wid >> 1, wc = wid & 1;
    int gid = lane >> 2, tig = lane & 3;
    int bh = blockIdx.y;
    int n0 = blockIdx.x * 128;
    size_t ab = (size_t)bh * NN;
    size_t vb = (size_t)bh * NTOK * DH;
    int ar = t >> 3, ac4 = t & 7;
    float acc[2][4][4] = {};
    for (int k0 = 0; k0 < NTOK; k0 += 32) {
        float4 pv[4], vv[2];
#pragma unroll
        for (int i = 0; i < 4; i++)
            pv[i] = *(const float4*)(g_attn + ab + (size_t)(n0 + ar + i*32)*NTOK + k0 + ac4*4);
#pragma unroll
        for (int i = 0; i < 2; i++) {
            int idx = i*256 + t;
            int r = idx >> 4, c4 = idx & 15;
            vv[i] = *(const float4*)(g_v + vb + (size_t)(k0+r)*DH + c4*4);
        }
        __syncthreads();
#pragma unroll
        for (int i = 0; i < 4; i++) {
            float* p = &Ps[ar + i*32][ac4*4];
            p[0]=f2t(pv[i].x); p[1]=f2t(pv[i].y); p[2]=f2t(pv[i].z); p[3]=f2t(pv[i].w);
        }
#pragma unroll
        for (int i = 0; i < 2; i++) {
            int idx = i*256 + t;
            int r = idx >> 4, c4 = idx & 15;
            float* p = &Vs[r][c4*4];
            p[0]=f2t(vv[i].x); p[1]=f2t(vv[i].y); p[2]=f2t(vv[i].z); p[3]=f2t(vv[i].w);
        }
        __syncthreads();
#pragma unroll
        for (int ks = 0; ks < 4; ks++) {
            int kk = ks*8;
            unsigned a[2][4], b[4][2];
#pragma unroll
            for (int mi = 0; mi < 2; mi++) {
                int r = wr*32 + mi*16 + gid;
                a[mi][0] = fb(Ps[r][kk+tig]);     a[mi][1] = fb(Ps[r+8][kk+tig]);
                a[mi][2] = fb(Ps[r][kk+tig+4]);   a[mi][3] = fb(Ps[r+8][kk+tig+4]);
            }
#pragma unroll
            for (int nj = 0; nj < 4; nj++) {
                int cb = wc*32 + nj*8 + gid;
                b[nj][0] = fb(Vs[kk+tig][cb]);    b[nj][1] = fb(Vs[kk+tig+4][cb]);
            }
#pragma unroll
            for (int mi = 0; mi < 2; mi++)
#pragma unroll
                for (int nj = 0; nj < 4; nj++)
                    mma_tf32(acc[mi][nj], a[mi], b[nj]);
        }
    }
#pragma unroll
    for (int mi = 0; mi < 2; mi++)
#pragma unroll
        for (int nj = 0; nj < 4; nj++) {
            int n = n0 + wr*32 + mi*16 + gid;
            int d = wc*32 + nj*8 + 2*tig;
            g_o[vb + (size_t)n*DH + d]       = acc[mi][nj][0];
            g_o[vb + (size_t)n*DH + d + 1]   = acc[mi][nj][1];
            g_o[vb + (size_t)(n+8)*DH + d]   = acc[mi][nj][2];
            g_o[vb + (size_t)(n+8)*DH + d+1] = acc[mi][nj][3];
        }
}

// ---------------- K7: Y = gather(O) @ w_out^T + b_out (tf32 mma) ----------------
// grid (DM/64, NB*NTOK/128): block tile 128 rows x 64 cols  [GRID FIXED]
__global__ void oproj_mma_kernel(const float* __restrict__ wout,
                                 const float* __restrict__ bout,
                                 float* __restrict__ out) {
    __shared__ float As[128][36];
    __shared__ float Bs[64][36];
    int t = threadIdx.x;
    int lane = t & 31, wid = t >> 5;
    int wr = wid >> 1, wc = wid & 1;
    int gid = lane >> 2, tig = lane & 3;
    int i0 = blockIdx.y * 128, o0 = blockIdx.x * 64;
    int ar = t >> 3, ac4 = t & 7;
    float acc[2][4][4] = {};
    for (int k0 = 0; k0 < DM; k0 += 32) {
        int h = k0 >> 6;
        int dd = (k0 & 63) + ac4*4;
        float4 av[4], bv[2];
#pragma unroll
        for (int i = 0; i < 4; i++) {
            int gi = i0 + ar + i*32;
            int b_ = gi >> 10, n = gi & 1023;
            av[i] = *(const float4*)(g_o + (((size_t)b_*NH + h)*NTOK + n)*DH + dd);
        }
#pragma unroll
        for (int i = 0; i < 2; i++)
            bv[i] = *(const float4*)(wout + (size_t)(o0 + ar + i*32)*DM + k0 + ac4*4);
        __syncthreads();
#pragma unroll
        for (int i = 0; i < 4; i++) {
            float* p = &As[ar + i*32][ac4*4];
            p[0]=f2t(av[i].x); p[1]=f2t(av[i].y); p[2]=f2t(av[i].z); p[3]=f2t(av[i].w);
        }
#pragma unroll
        for (int i = 0; i < 2; i++) {
            float* p = &Bs[ar + i*32][ac4*4];
            p[0]=f2t(bv[i].x); p[1]=f2t(bv[i].y); p[2]=f2t(bv[i].z); p[3]=f2t(bv[i].w);
        }
        __syncthreads();
#pragma unroll
        for (int ks = 0; ks < 4; ks++) {
            int kk = ks*8;
            unsigned a[2][4], b[4][2];
#pragma unroll
            for (int mi = 0; mi < 2; mi++) {
                int r = wr*32 + mi*16 + gid;
                a[mi][0] = fb(As[r][kk+tig]);     a[mi][1] = fb(As[r+8][kk+tig]);
                a[mi][2] = fb(As[r][kk+tig+4]);   a[mi][3] = fb(As[r+8][kk+tig+4]);
            }
#pragma unroll
            for (int nj = 0; nj < 4; nj++) {
                int cb = wc*32 + nj*8 + gid;
                b[nj][0] = fb(Bs[cb][kk+tig]);    b[nj][1] = fb(Bs[cb][kk+tig+4]);
            }
#pragma unroll
            for (int mi = 0; mi < 2; mi++)
#pragma unroll
                for (int nj = 0; nj < 4; nj++)
                    mma_tf32(acc[mi][nj], a[mi], b[nj]);
        }
    }
#pragma unroll
    for (int mi = 0; mi < 2; mi++)
#pragma unroll
        for (int nj = 0; nj < 4; nj++) {
            int gi = i0 + wr*32 + mi*16 + gid;
            int o  = o0 + wc*32 + nj*8 + 2*tig;
            out[(size_t)gi*DM + o]       = acc[mi][nj][0] + bout[o];
            out[(size_t)gi*DM + o + 1]   = acc[mi][nj][1] + bout[o+1];
            out[(size_t)(gi+8)*DM + o]   = acc[mi][nj][2] + bout[o];
            out[(size_t)(gi+8)*DM + o+1] = acc[mi][nj][3] + bout[o+1];
        }
}

// ---------------- launch ----------------
extern "C" void kernel_launch(void* const* d_in, const int* in_sizes, int n_in,
                              void* d_out, int out_size) {
    const float* x      = (const float*)d_in[0];
    const float* ln_g   = (const float*)d_in[1];
    const float* ln_b   = (const float*)d_in[2];
    const float* w_qkv  = (const float*)d_in[3];
    const float* w_out  = (const float*)d_in[4];
    const float* b_out  = (const float*)d_in[5];
    const float* theta  = (const float*)d_in[6];
    const float* gnn_w  = (const float*)d_in[7];
    float* out = (float*)d_out;

    ln_kernel<<<NB*NTOK, 256>>>(x, ln_g, ln_b);
    qkv_mma_kernel<<<dim3(36, NB*NTOK/128), 256>>>(w_qkv);
    mcompute_kernel<<<1, 160>>>(theta, gnn_w);
    attn_mma_kernel<<<dim3(NTOK/64, BHH), 128>>>();
    pmix_kernel<<<(NB*NN)/256, 256>>>();
    pv_mma_kernel<<<dim3(NTOK/128, BHH), 256>>>();
    oproj_mma_kernel<<<dim3(DM/64, NB*NTOK/128), 256>>>(w_out, b_out, out);
}

// round 7
// speedup vs baseline: 2.1740x; 1.0516x over previous
#include <cuda_runtime.h>

#define NB    2
#define NTOK  1024
#define DM    768
#define NH    12
#define DH    64
#define BHH   (NB*NH)
#define NN    (NTOK*NTOK)
#define QK_SCALE 0.125f

// ---------------- scratch (static device memory; no allocations) ----------------
__device__ float g_xn[NB*NTOK*DM];
__device__ float g_q[BHH*NTOK*DH];
__device__ float g_k[BHH*NTOK*DH];
__device__ float g_v[BHH*NTOK*DH];
__device__ float g_o[BHH*NTOK*DH];
__device__ float g_rsinv[BHH*NTOK];
__device__ float g_M[NH*NH];
__device__ float g_attn[(size_t)BHH*NN];   // ~100.7 MB

// ---------------- tf32 helpers ----------------
__device__ __forceinline__ float f2t(float x) {
    unsigned u;
    asm("cvt.rna.tf32.f32 %0, %1;" : "=r"(u) : "f"(x));
    return __uint_as_float(u);
}
__device__ __forceinline__ unsigned fb(float x) { return __float_as_uint(x); }

__device__ __forceinline__ void mma_tf32(float c[4], const unsigned a[4], const unsigned b[2]) {
    asm volatile(
        "mma.sync.aligned.m16n8k8.row.col.f32.tf32.tf32.f32 "
        "{%0,%1,%2,%3}, {%4,%5,%6,%7}, {%8,%9}, {%0,%1,%2,%3};\n"
        : "+f"(c[0]), "+f"(c[1]), "+f"(c[2]), "+f"(c[3])
        : "r"(a[0]), "r"(a[1]), "r"(a[2]), "r"(a[3]), "r"(b[0]), "r"(b[1]));
}

// ---------------- K1: LayerNorm (proven) ----------------
__global__ void ln_kernel(const float* __restrict__ x,
                          const float* __restrict__ gamma,
                          const float* __restrict__ beta) {
    int row = blockIdx.x;
    const float* xr = x + (size_t)row * DM;
    int t = threadIdx.x;
    float v[3];
    float s = 0.f, ss = 0.f;
#pragma unroll
    for (int i = 0; i < 3; i++) {
        v[i] = xr[t + i*256];
        s += v[i]; ss += v[i]*v[i];
    }
#pragma unroll
    for (int o = 16; o > 0; o >>= 1) {
        s  += __shfl_xor_sync(0xffffffffu, s,  o);
        ss += __shfl_xor_sync(0xffffffffu, ss, o);
    }
    __shared__ float sm1[8], sm2[8];
    int lane = t & 31, w = t >> 5;
    if (lane == 0) { sm1[w] = s; sm2[w] = ss; }
    __syncthreads();
    if (t == 0) {
        float a = 0.f, b = 0.f;
#pragma unroll
        for (int i = 0; i < 8; i++) { a += sm1[i]; b += sm2[i]; }
        sm1[0] = a; sm2[0] = b;
    }
    __syncthreads();
    float mean = sm1[0] * (1.f/DM);
    float var  = sm2[0] * (1.f/DM) - mean*mean;
    float inv  = rsqrtf(var + 1e-5f);
    float* outr = g_xn + (size_t)row * DM;
#pragma unroll
    for (int i = 0; i < 3; i++) {
        int c = t + i*256;
        outr[c] = (v[i]-mean)*inv*gamma[c] + beta[c];
    }
}

// ---------------- K2: QKV GEMM (tf32 mma)  C[2048,2304] = xn @ w_qkv^T ----------------
// grid (18, 16): block tile 128 rows x 128 cols. 256 thr = 8 warps (4x2), warp 32x64.
__device__ __forceinline__ void qkv_store(int gi, int gj, float v) {
    int b = gi >> 10, n = gi & 1023;
    int which = gj / DM;
    int r = gj - which*DM;
    int h = r >> 6, d = r & 63;
    float* dst = (which == 0) ? g_q : (which == 1 ? g_k : g_v);
    dst[(((size_t)b*NH + h)*NTOK + n)*DH + d] = v;
}

__global__ void qkv_mma_kernel(const float* __restrict__ wqkv) {
    __shared__ float As[128][36];
    __shared__ float Bs[128][36];
    int t = threadIdx.x;
    int lane = t & 31, wid = t >> 5;
    int wr = wid >> 1, wc = wid & 1;
    int gid = lane >> 2, tig = lane & 3;
    int i0 = blockIdx.y * 128, j0 = blockIdx.x * 128;
    int ar = t >> 3, ac4 = t & 7;
    float acc[2][8][4] = {};
    for (int k0 = 0; k0 < DM; k0 += 32) {
        float4 av[4], bv[4];
#pragma unroll
        for (int i = 0; i < 4; i++)
            av[i] = *(const float4*)(g_xn + (size_t)(i0 + ar + i*32)*DM + k0 + ac4*4);
#pragma unroll
        for (int i = 0; i < 4; i++)
            bv[i] = *(const float4*)(wqkv + (size_t)(j0 + ar + i*32)*DM + k0 + ac4*4);
        __syncthreads();
#pragma unroll
        for (int i = 0; i < 4; i++) {
            float* p = &As[ar + i*32][ac4*4];
            p[0]=f2t(av[i].x); p[1]=f2t(av[i].y); p[2]=f2t(av[i].z); p[3]=f2t(av[i].w);
        }
#pragma unroll
        for (int i = 0; i < 4; i++) {
            float* p = &Bs[ar + i*32][ac4*4];
            p[0]=f2t(bv[i].x); p[1]=f2t(bv[i].y); p[2]=f2t(bv[i].z); p[3]=f2t(bv[i].w);
        }
        __syncthreads();
#pragma unroll
        for (int ks = 0; ks < 4; ks++) {
            int kk = ks*8;
            unsigned a[2][4], b[8][2];
#pragma unroll
            for (int mi = 0; mi < 2; mi++) {
                int r = wr*32 + mi*16 + gid;
                a[mi][0] = fb(As[r][kk+tig]);     a[mi][1] = fb(As[r+8][kk+tig]);
                a[mi][2] = fb(As[r][kk+tig+4]);   a[mi][3] = fb(As[r+8][kk+tig+4]);
            }
#pragma unroll
            for (int nj = 0; nj < 8; nj++) {
                int cb = wc*64 + nj*8 + gid;
                b[nj][0] = fb(Bs[cb][kk+tig]);    b[nj][1] = fb(Bs[cb][kk+tig+4]);
            }
#pragma unroll
            for (int mi = 0; mi < 2; mi++)
#pragma unroll
                for (int nj = 0; nj < 8; nj++)
                    mma_tf32(acc[mi][nj], a[mi], b[nj]);
        }
    }
#pragma unroll
    for (int mi = 0; mi < 2; mi++)
#pragma unroll
        for (int nj = 0; nj < 8; nj++) {
            int gi = i0 + wr*32 + mi*16 + gid;
            int gj = j0 + wc*64 + nj*8 + 2*tig;
            qkv_store(gi,     gj,     acc[mi][nj][0]);
            qkv_store(gi,     gj + 1, acc[mi][nj][1]);
            qkv_store(gi + 8, gj,     acc[mi][nj][2]);
            qkv_store(gi + 8, gj + 1, acc[mi][nj][3]);
        }
}

// ---------------- K3: attn (tf32 mma) E = exp(scale*Q K^T), rowsums ----------------
// grid (NTOK/64, BHH), 256 thr = 8 warps (2 wr x 4 wc), warp tile 32n x 16m, m-loop 64.
__global__ void attn_mma_kernel() {
    __shared__ float Qs[64][68];   // Q tile, reused as E staging after qf hoist
    __shared__ float Ks[64][68];
    __shared__ float ssum[64];
    int t = threadIdx.x;
    int lane = t & 31, wid = t >> 5;
    int wr = wid >> 2, wc = wid & 3;
    int gid = lane >> 2, tig = lane & 3;
    int bh = blockIdx.y;
    int n0 = blockIdx.x * 64;
    size_t qb = (size_t)bh * NTOK * DH;
    size_t ab = (size_t)bh * NN;

    // load Q tile (64x64) as tf32: 4 float4 per thread
#pragma unroll
    for (int i = 0; i < 4; i++) {
        int idx = i*256 + t;
        int r = idx >> 4, c4 = idx & 15;
        float4 q4 = *(const float4*)(g_q + qb + (size_t)(n0+r)*DH + c4*4);
        float* p = &Qs[r][c4*4];
        p[0]=f2t(q4.x); p[1]=f2t(q4.y); p[2]=f2t(q4.z); p[3]=f2t(q4.w);
    }
    if (t < 64) ssum[t] = 0.f;
    __syncthreads();

    // hoist Q fragments for all 8 k-steps
    unsigned qf[2][8][4];
#pragma unroll
    for (int mi = 0; mi < 2; mi++) {
        int r = wr*32 + mi*16 + gid;
#pragma unroll
        for (int ks = 0; ks < 8; ks++) {
            int kk = ks*8;
            qf[mi][ks][0] = fb(Qs[r][kk+tig]);     qf[mi][ks][1] = fb(Qs[r+8][kk+tig]);
            qf[mi][ks][2] = fb(Qs[r][kk+tig+4]);   qf[mi][ks][3] = fb(Qs[r+8][kk+tig+4]);
        }
    }
    float rs[2][2] = {};

    for (int m0 = 0; m0 < NTOK; m0 += 64) {
        float4 kv[4];
#pragma unroll
        for (int i = 0; i < 4; i++) {
            int idx = i*256 + t;
            int r = idx >> 4, c4 = idx & 15;
            kv[i] = *(const float4*)(g_k + qb + (size_t)(m0+r)*DH + c4*4);
        }
        __syncthreads();   // prev write-out done (Qs free), prev MMA reads of Ks done
#pragma unroll
        for (int i = 0; i < 4; i++) {
            int idx = i*256 + t;
            int r = idx >> 4, c4 = idx & 15;
            float* p = &Ks[r][c4*4];
            p[0]=f2t(kv[i].x); p[1]=f2t(kv[i].y); p[2]=f2t(kv[i].z); p[3]=f2t(kv[i].w);
        }
        __syncthreads();
        float acc[2][2][4] = {};
#pragma unroll
        for (int ks = 0; ks < 8; ks++) {
            int kk = ks*8;
            unsigned b[2][2];
#pragma unroll
            for (int nj = 0; nj < 2; nj++) {
                int cb = wc*16 + nj*8 + gid;
                b[nj][0] = fb(Ks[cb][kk+tig]);  b[nj][1] = fb(Ks[cb][kk+tig+4]);
            }
#pragma unroll
            for (int mi = 0; mi < 2; mi++)
#pragma unroll
                for (int nj = 0; nj < 2; nj++)
                    mma_tf32(acc[mi][nj], qf[mi][ks], b[nj]);
        }
        // exp + rowsum + stage into Qs as E[n-local][m-local]
#pragma unroll
        for (int mi = 0; mi < 2; mi++) {
            int r = wr*32 + mi*16 + gid;
#pragma unroll
            for (int nj = 0; nj < 2; nj++) {
                int c = wc*16 + nj*8 + 2*tig;
                float e0 = __expf(acc[mi][nj][0]*QK_SCALE);
                float e1 = __expf(acc[mi][nj][1]*QK_SCALE);
                float e2 = __expf(acc[mi][nj][2]*QK_SCALE);
                float e3 = __expf(acc[mi][nj][3]*QK_SCALE);
                Qs[r][c] = e0;   Qs[r][c+1] = e1;
                Qs[r+8][c] = e2; Qs[r+8][c+1] = e3;
                rs[mi][0] += e0 + e1;
                rs[mi][1] += e2 + e3;
            }
        }
        __syncthreads();
        // coalesced write-out: warp wid handles rows wid*8..+7
#pragma unroll
        for (int rr = 0; rr < 8; rr++) {
            int row = wid*8 + rr;
            float v0 = Qs[row][lane];
            float v1 = Qs[row][lane+32];
            float* dstp = g_attn + ab + (size_t)(n0+row)*NTOK + m0;
            dstp[lane]    = v0;
            dstp[lane+32] = v1;
        }
    }
    __syncthreads();
#pragma unroll
    for (int mi = 0; mi < 2; mi++) {
        int r = wr*32 + mi*16 + gid;
        atomicAdd(&ssum[r],   rs[mi][0]);
        atomicAdd(&ssum[r+8], rs[mi][1]);
    }
    __syncthreads();
    if (t < 64) g_rsinv[bh*NTOK + n0 + t] = 1.0f / ssum[t];
}

// ---------------- K4: M = (-0.5*theta) @ gnn_w ----------------
__global__ void mcompute_kernel(const float* __restrict__ theta,
                                const float* __restrict__ gw) {
    int idx = threadIdx.x;
    if (idx < NH*NH) {
        int i = idx / NH, k = idx - i*NH;
        float s = 0.f;
#pragma unroll
        for (int j = 0; j < NH; j++) s += theta[i*NH+j] * gw[j*NH+k];
        g_M[idx] = -0.5f * s;
    }
}

// ---------------- K5: in-place P = a + relu(M @ a), float4 version ----------------
// grid 2048 x 256 thr, each thread: 4 consecutive m positions
__global__ void pmix_kernel() {
    __shared__ float Ms[NH*NH];
    if (threadIdx.x < NH*NH) Ms[threadIdx.x] = g_M[threadIdx.x];
    __syncthreads();
    size_t pos4 = (size_t)blockIdx.x * 256 + threadIdx.x;   // < NB*NN/4 = 524288
    int b   = (int)(pos4 >> 18);                 // NN/4 = 262144 = 2^18
    int nm4 = (int)(pos4 & (size_t)(NN/4 - 1));
    int n   = nm4 >> 8;                          // (nm4*4) >> 10
    size_t base = (size_t)b * NH * NN + (size_t)nm4 * 4;
    float4 a[NH];
#pragma unroll
    for (int h = 0; h < NH; h++) {
        float inv = g_rsinv[(b*NH + h)*NTOK + n];
        float4 e = *(const float4*)(g_attn + base + (size_t)h*NN);
        a[h] = make_float4(e.x*inv, e.y*inv, e.z*inv, e.w*inv);
    }
#pragma unroll
    for (int i = 0; i < NH; i++) {
        float sx = 0.f, sy = 0.f, sz = 0.f, sw = 0.f;
#pragma unroll
        for (int k = 0; k < NH; k++) {
            float m = Ms[i*NH+k];
            sx += m*a[k].x; sy += m*a[k].y; sz += m*a[k].z; sw += m*a[k].w;
        }
        float4 o = make_float4(a[i].x + fmaxf(sx, 0.f), a[i].y + fmaxf(sy, 0.f),
                               a[i].z + fmaxf(sz, 0.f), a[i].w + fmaxf(sw, 0.f));
        *(float4*)(g_attn + base + (size_t)i*NN) = o;
    }
}

// ---------------- K6: O = P @ V per bh (tf32 mma), grid (NTOK/128, BHH) ----------------
__global__ void pv_mma_kernel() {
    __shared__ float Ps[128][36];
    __shared__ float Vs[32][68];
    int t = threadIdx.x;
    int lane = t & 31, wid = t >> 5;
    int wr = wid >> 1, wc = wid & 1;
    int gid = lane >> 2, tig = lane & 3;
    int bh = blockIdx.y;
    int n0 = blockIdx.x * 128;
    size_t ab = (size_t)bh * NN;
    size_t vb = (size_t)bh * NTOK * DH;
    int ar = t >> 3, ac4 = t & 7;
    float acc[2][4][4] = {};
    for (int k0 = 0; k0 < NTOK; k0 += 32) {
        float4 pv[4], vv[2];
#pragma unroll
        for (int i = 0; i < 4; i++)
            pv[i] = *(const float4*)(g_attn + ab + (size_t)(n0 + ar + i*32)*NTOK + k0 + ac4*4);
#pragma unroll
        for (int i = 0; i < 2; i++) {
            int idx = i*256 + t;
            int r = idx >> 4, c4 = idx & 15;
            vv[i] = *(const float4*)(g_v + vb + (size_t)(k0+r)*DH + c4*4);
        }
        __syncthreads();
#pragma unroll
        for (int i = 0; i < 4; i++) {
            float* p = &Ps[ar + i*32][ac4*4];
            p[0]=f2t(pv[i].x); p[1]=f2t(pv[i].y); p[2]=f2t(pv[i].z); p[3]=f2t(pv[i].w);
        }
#pragma unroll
        for (int i = 0; i < 2; i++) {
            int idx = i*256 + t;
            int r = idx >> 4, c4 = idx & 15;
            float* p = &Vs[r][c4*4];
            p[0]=f2t(vv[i].x); p[1]=f2t(vv[i].y); p[2]=f2t(vv[i].z); p[3]=f2t(vv[i].w);
        }
        __syncthreads();
#pragma unroll
        for (int ks = 0; ks < 4; ks++) {
            int kk = ks*8;
            unsigned a[2][4], b[4][2];
#pragma unroll
            for (int mi = 0; mi < 2; mi++) {
                int r = wr*32 + mi*16 + gid;
                a[mi][0] = fb(Ps[r][kk+tig]);     a[mi][1] = fb(Ps[r+8][kk+tig]);
                a[mi][2] = fb(Ps[r][kk+tig+4]);   a[mi][3] = fb(Ps[r+8][kk+tig+4]);
            }
#pragma unroll
            for (int nj = 0; nj < 4; nj++) {
                int cb = wc*32 + nj*8 + gid;
                b[nj][0] = fb(Vs[kk+tig][cb]);    b[nj][1] = fb(Vs[kk+tig+4][cb]);
            }
#pragma unroll
            for (int mi = 0; mi < 2; mi++)
#pragma unroll
                for (int nj = 0; nj < 4; nj++)
                    mma_tf32(acc[mi][nj], a[mi], b[nj]);
        }
    }
#pragma unroll
    for (int mi = 0; mi < 2; mi++)
#pragma unroll
        for (int nj = 0; nj < 4; nj++) {
            int n = n0 + wr*32 + mi*16 + gid;
            int d = wc*32 + nj*8 + 2*tig;
            g_o[vb + (size_t)n*DH + d]       = acc[mi][nj][0];
            g_o[vb + (size_t)n*DH + d + 1]   = acc[mi][nj][1];
            g_o[vb + (size_t)(n+8)*DH + d]   = acc[mi][nj][2];
            g_o[vb + (size_t)(n+8)*DH + d+1] = acc[mi][nj][3];
        }
}

// ---------------- K7: Y = gather(O) @ w_out^T + b_out (tf32 mma) ----------------
// grid (DM/64, NB*NTOK/128): block tile 128 rows x 64 cols
__global__ void oproj_mma_kernel(const float* __restrict__ wout,
                                 const float* __restrict__ bout,
                                 float* __restrict__ out) {
    __shared__ float As[128][36];
    __shared__ float Bs[64][36];
    int t = threadIdx.x;
    int lane = t & 31, wid = t >> 5;
    int wr = wid >> 1, wc = wid & 1;
    int gid = lane >> 2, tig = lane & 3;
    int i0 = blockIdx.y * 128, o0 = blockIdx.x * 64;
    int ar = t >> 3, ac4 = t & 7;
    float acc[2][4][4] = {};
    for (int k0 = 0; k0 < DM; k0 += 32) {
        int h = k0 >> 6;
        int dd = (k0 & 63) + ac4*4;
        float4 av[4], bv[2];
#pragma unroll
        for (int i = 0; i < 4; i++) {
            int gi = i0 + ar + i*32;
            int b_ = gi >> 10, n = gi & 1023;
            av[i] = *(const float4*)(g_o + (((size_t)b_*NH + h)*NTOK + n)*DH + dd);
        }
#pragma unroll
        for (int i = 0; i < 2; i++)
            bv[i] = *(const float4*)(wout + (size_t)(o0 + ar + i*32)*DM + k0 + ac4*4);
        __syncthreads();
#pragma unroll
        for (int i = 0; i < 4; i++) {
            float* p = &As[ar + i*32][ac4*4];
            p[0]=f2t(av[i].x); p[1]=f2t(av[i].y); p[2]=f2t(av[i].z); p[3]=f2t(av[i].w);
        }
#pragma unroll
        for (int i = 0; i < 2; i++) {
            float* p = &Bs[ar + i*32][ac4*4];
            p[0]=f2t(bv[i].x); p[1]=f2t(bv[i].y); p[2]=f2t(bv[i].z); p[3]=f2t(bv[i].w);
        }
        __syncthreads();
#pragma unroll
        for (int ks = 0; ks < 4; ks++) {
            int kk = ks*8;
            unsigned a[2][4], b[4][2];
#pragma unroll
            for (int mi = 0; mi < 2; mi++) {
                int r = wr*32 + mi*16 + gid;
                a[mi][0] = fb(As[r][kk+tig]);     a[mi][1] = fb(As[r+8][kk+tig]);
                a[mi][2] = fb(As[r][kk+tig+4]);   a[mi][3] = fb(As[r+8][kk+tig+4]);
            }
#pragma unroll
            for (int nj = 0; nj < 4; nj++) {
                int cb = wc*32 + nj*8 + gid;
                b[nj][0] = fb(Bs[cb][kk+tig]);    b[nj][1] = fb(Bs[cb][kk+tig+4]);
            }
#pragma unroll
            for (int mi = 0; mi < 2; mi++)
#pragma unroll
                for (int nj = 0; nj < 4; nj++)
                    mma_tf32(acc[mi][nj], a[mi], b[nj]);
        }
    }
#pragma unroll
    for (int mi = 0; mi < 2; mi++)
#pragma unroll
        for (int nj = 0; nj < 4; nj++) {
            int gi = i0 + wr*32 + mi*16 + gid;
            int o  = o0 + wc*32 + nj*8 + 2*tig;
            out[(size_t)gi*DM + o]       = acc[mi][nj][0] + bout[o];
            out[(size_t)gi*DM + o + 1]   = acc[mi][nj][1] + bout[o+1];
            out[(size_t)(gi+8)*DM + o]   = acc[mi][nj][2] + bout[o];
            out[(size_t)(gi+8)*DM + o+1] = acc[mi][nj][3] + bout[o+1];
        }
}

// ---------------- launch ----------------
extern "C" void kernel_launch(void* const* d_in, const int* in_sizes, int n_in,
                              void* d_out, int out_size) {
    const float* x      = (const float*)d_in[0];
    const float* ln_g   = (const float*)d_in[1];
    const float* ln_b   = (const float*)d_in[2];
    const float* w_qkv  = (const float*)d_in[3];
    const float* w_out  = (const float*)d_in[4];
    const float* b_out  = (const float*)d_in[5];
    const float* theta  = (const float*)d_in[6];
    const float* gnn_w  = (const float*)d_in[7];
    float* out = (float*)d_out;

    ln_kernel<<<NB*NTOK, 256>>>(x, ln_g, ln_b);
    qkv_mma_kernel<<<dim3(3*DM/128, NB*NTOK/128), 256>>>(w_qkv);      // (18,16)
    mcompute_kernel<<<1, 160>>>(theta, gnn_w);
    attn_mma_kernel<<<dim3(NTOK/64, BHH), 256>>>();                    // (16,24)
    pmix_kernel<<<(NB*NN/4)/256, 256>>>();                             // 2048
    pv_mma_kernel<<<dim3(NTOK/128, BHH), 256>>>();                     // (8,24)
    oproj_mma_kernel<<<dim3(DM/64, NB*NTOK/128), 256>>>(w_out, b_out, out); // (12,16)
}

// round 9
// speedup vs baseline: 2.3045x; 1.0600x over previous
#include <cuda_runtime.h>

#define NB    2
#define NTOK  1024
#define DM    768
#define NH    12
#define DH    64
#define BHH   (NB*NH)
#define NN    (NTOK*NTOK)
#define QK_SCALE 0.125f

// ---------------- scratch (static device memory; no allocations) ----------------
__device__ float g_xn[NB*NTOK*DM];
__device__ float g_q[BHH*NTOK*DH];
__device__ float g_k[BHH*NTOK*DH];
__device__ float g_v[BHH*NTOK*DH];
__device__ float g_o[BHH*NTOK*DH];
__device__ float g_rsinv[BHH*NTOK];
__device__ float g_M[NH*NH];
__device__ float g_attn[(size_t)BHH*NN];   // ~100.7 MB

// ---------------- tf32 helpers ----------------
__device__ __forceinline__ float f2t(float x) {
    unsigned u;
    asm("cvt.rna.tf32.f32 %0, %1;" : "=r"(u) : "f"(x));
    return __uint_as_float(u);
}
__device__ __forceinline__ unsigned fb(float x) { return __float_as_uint(x); }

__device__ __forceinline__ void mma_tf32(float c[4], const unsigned a[4], const unsigned b[2]) {
    asm volatile(
        "mma.sync.aligned.m16n8k8.row.col.f32.tf32.tf32.f32 "
        "{%0,%1,%2,%3}, {%4,%5,%6,%7}, {%8,%9}, {%0,%1,%2,%3};\n"
        : "+f"(c[0]), "+f"(c[1]), "+f"(c[2]), "+f"(c[3])
        : "r"(a[0]), "r"(a[1]), "r"(a[2]), "r"(a[3]), "r"(b[0]), "r"(b[1]));
}

// ---------------- K1: LayerNorm (proven) ----------------
__global__ void ln_kernel(const float* __restrict__ x,
                          const float* __restrict__ gamma,
                          const float* __restrict__ beta) {
    int row = blockIdx.x;
    const float* xr = x + (size_t)row * DM;
    int t = threadIdx.x;
    float v[3];
    float s = 0.f, ss = 0.f;
#pragma unroll
    for (int i = 0; i < 3; i++) {
        v[i] = xr[t + i*256];
        s += v[i]; ss += v[i]*v[i];
    }
#pragma unroll
    for (int o = 16; o > 0; o >>= 1) {
        s  += __shfl_xor_sync(0xffffffffu, s,  o);
        ss += __shfl_xor_sync(0xffffffffu, ss, o);
    }
    __shared__ float sm1[8], sm2[8];
    int lane = t & 31, w = t >> 5;
    if (lane == 0) { sm1[w] = s; sm2[w] = ss; }
    __syncthreads();
    if (t == 0) {
        float a = 0.f, b = 0.f;
#pragma unroll
        for (int i = 0; i < 8; i++) { a += sm1[i]; b += sm2[i]; }
        sm1[0] = a; sm2[0] = b;
    }
    __syncthreads();
    float mean = sm1[0] * (1.f/DM);
    float var  = sm2[0] * (1.f/DM) - mean*mean;
    float inv  = rsqrtf(var + 1e-5f);
    float* outr = g_xn + (size_t)row * DM;
#pragma unroll
    for (int i = 0; i < 3; i++) {
        int c = t + i*256;
        outr[c] = (v[i]-mean)*inv*gamma[c] + beta[c];
    }
}

// ---------------- K2: QKV GEMM (tf32 mma)  C[2048,2304] = xn @ w_qkv^T ----------------
// grid (18, 16): block tile 128x128. 256 thr = 8 warps (4x2), warp 32x64.  (proven R6)
__device__ __forceinline__ void qkv_store(int gi, int gj, float v) {
    int b = gi >> 10, n = gi & 1023;
    int which = gj / DM;
    int r = gj - which*DM;
    int h = r >> 6, d = r & 63;
    float* dst = (which == 0) ? g_q : (which == 1 ? g_k : g_v);
    dst[(((size_t)b*NH + h)*NTOK + n)*DH + d] = v;
}

__global__ void qkv_mma_kernel(const float* __restrict__ wqkv) {
    __shared__ float As[128][36];
    __shared__ float Bs[128][36];
    int t = threadIdx.x;
    int lane = t & 31, wid = t >> 5;
    int wr = wid >> 1, wc = wid & 1;
    int gid = lane >> 2, tig = lane & 3;
    int i0 = blockIdx.y * 128, j0 = blockIdx.x * 128;
    int ar = t >> 3, ac4 = t & 7;
    float acc[2][8][4] = {};
    for (int k0 = 0; k0 < DM; k0 += 32) {
        float4 av[4], bv[4];
#pragma unroll
        for (int i = 0; i < 4; i++)
            av[i] = *(const float4*)(g_xn + (size_t)(i0 + ar + i*32)*DM + k0 + ac4*4);
#pragma unroll
        for (int i = 0; i < 4; i++)
            bv[i] = *(const float4*)(wqkv + (size_t)(j0 + ar + i*32)*DM + k0 + ac4*4);
        __syncthreads();
#pragma unroll
        for (int i = 0; i < 4; i++) {
            float* p = &As[ar + i*32][ac4*4];
            p[0]=f2t(av[i].x); p[1]=f2t(av[i].y); p[2]=f2t(av[i].z); p[3]=f2t(av[i].w);
        }
#pragma unroll
        for (int i = 0; i < 4; i++) {
            float* p = &Bs[ar + i*32][ac4*4];
            p[0]=f2t(bv[i].x); p[1]=f2t(bv[i].y); p[2]=f2t(bv[i].z); p[3]=f2t(bv[i].w);
        }
        __syncthreads();
#pragma unroll
        for (int ks = 0; ks < 4; ks++) {
            int kk = ks*8;
            unsigned a[2][4], b[8][2];
#pragma unroll
            for (int mi = 0; mi < 2; mi++) {
                int r = wr*32 + mi*16 + gid;
                a[mi][0] = fb(As[r][kk+tig]);     a[mi][1] = fb(As[r+8][kk+tig]);
                a[mi][2] = fb(As[r][kk+tig+4]);   a[mi][3] = fb(As[r+8][kk+tig+4]);
            }
#pragma unroll
            for (int nj = 0; nj < 8; nj++) {
                int cb = wc*64 + nj*8 + gid;
                b[nj][0] = fb(Bs[cb][kk+tig]);    b[nj][1] = fb(Bs[cb][kk+tig+4]);
            }
#pragma unroll
            for (int mi = 0; mi < 2; mi++)
#pragma unroll
                for (int nj = 0; nj < 8; nj++)
                    mma_tf32(acc[mi][nj], a[mi], b[nj]);
        }
    }
#pragma unroll
    for (int mi = 0; mi < 2; mi++)
#pragma unroll
        for (int nj = 0; nj < 8; nj++) {
            int gi = i0 + wr*32 + mi*16 + gid;
            int gj = j0 + wc*64 + nj*8 + 2*tig;
            qkv_store(gi,     gj,     acc[mi][nj][0]);
            qkv_store(gi,     gj + 1, acc[mi][nj][1]);
            qkv_store(gi + 8, gj,     acc[mi][nj][2]);
            qkv_store(gi + 8, gj + 1, acc[mi][nj][3]);
        }
}

// ---------------- K3: attn v3 (tf32 mma) ----------------
// grid (NTOK/128, BHH), 256 thr = 8 warps = 2 groups x 4 warps.
// Each group: 64 n-rows, warp tile 32n x 32m (R4-proven geometry).
// K tile shared across both groups; E stored direct to gmem (no smem staging).
__global__ void attn_mma_kernel() {
    __shared__ float Ks[64][68];     // phase 1: Q staging; main loop: K tile
    __shared__ float ssum[128];
    int t = threadIdx.x;
    int lane = t & 31, wid = t >> 5;
    int wg = wid >> 2;               // n-row group: 0 or 1
    int wl = wid & 3;
    int wr = wl >> 1, wc = wl & 1;   // 2x2 within group
    int gid = lane >> 2, tig = lane & 3;
    int bh = blockIdx.y;
    int n0 = blockIdx.x * 128;
    size_t qb = (size_t)bh * NTOK * DH;
    size_t ab = (size_t)bh * NN;

    if (t < 128) ssum[t] = 0.f;

    // two-phase Q fragment hoist through the shared buffer
    unsigned qf[2][8][4];
#pragma unroll
    for (int g = 0; g < 2; g++) {
        __syncthreads();     // buffer free (prev phase hoist done)
#pragma unroll
        for (int i = 0; i < 4; i++) {
            int idx = i*256 + t;
            int r = idx >> 4, c4 = idx & 15;
            float4 q4 = *(const float4*)(g_q + qb + (size_t)(n0 + g*64 + r)*DH + c4*4);
            float* p = &Ks[r][c4*4];
            p[0]=f2t(q4.x); p[1]=f2t(q4.y); p[2]=f2t(q4.z); p[3]=f2t(q4.w);
        }
        __syncthreads();
        if (wg == g) {
#pragma unroll
            for (int mi = 0; mi < 2; mi++) {
                int r = wr*32 + mi*16 + gid;
#pragma unroll
                for (int ks = 0; ks < 8; ks++) {
                    int kk = ks*8;
                    qf[mi][ks][0] = fb(Ks[r][kk+tig]);     qf[mi][ks][1] = fb(Ks[r+8][kk+tig]);
                    qf[mi][ks][2] = fb(Ks[r][kk+tig+4]);   qf[mi][ks][3] = fb(Ks[r+8][kk+tig+4]);
                }
            }
        }
    }

    float rs[2][2] = {};
    for (int m0 = 0; m0 < NTOK; m0 += 64) {
        float4 kv[4];
#pragma unroll
        for (int i = 0; i < 4; i++) {
            int idx = i*256 + t;
            int r = idx >> 4, c4 = idx & 15;
            kv[i] = *(const float4*)(g_k + qb + (size_t)(m0+r)*DH + c4*4);
        }
        __syncthreads();   // all warps done with previous Ks (MMA reads precede this point)
#pragma unroll
        for (int i = 0; i < 4; i++) {
            int idx = i*256 + t;
            int r = idx >> 4, c4 = idx & 15;
            float* p = &Ks[r][c4*4];
            p[0]=f2t(kv[i].x); p[1]=f2t(kv[i].y); p[2]=f2t(kv[i].z); p[3]=f2t(kv[i].w);
        }
        __syncthreads();
        float acc[2][4][4] = {};
#pragma unroll
        for (int ks = 0; ks < 8; ks++) {
            int kk = ks*8;
            unsigned b[4][2];
#pragma unroll
            for (int nj = 0; nj < 4; nj++) {
                int cb = wc*32 + nj*8 + gid;
                b[nj][0] = fb(Ks[cb][kk+tig]);  b[nj][1] = fb(Ks[cb][kk+tig+4]);
            }
#pragma unroll
            for (int mi = 0; mi < 2; mi++)
#pragma unroll
                for (int nj = 0; nj < 4; nj++)
                    mma_tf32(acc[mi][nj], qf[mi][ks], b[nj]);
        }
        // exp + rowsum + direct sector-coalesced float2 stores
#pragma unroll
        for (int mi = 0; mi < 2; mi++) {
            int gn = n0 + wg*64 + wr*32 + mi*16 + gid;
#pragma unroll
            for (int nj = 0; nj < 4; nj++) {
                int m = m0 + wc*32 + nj*8 + 2*tig;
                float e0 = __expf(acc[mi][nj][0]*QK_SCALE);
                float e1 = __expf(acc[mi][nj][1]*QK_SCALE);
                float e2 = __expf(acc[mi][nj][2]*QK_SCALE);
                float e3 = __expf(acc[mi][nj][3]*QK_SCALE);
                rs[mi][0] += e0 + e1;
                rs[mi][1] += e2 + e3;
                *(float2*)(g_attn + ab + (size_t)gn*NTOK + m)     = make_float2(e0, e1);
                *(float2*)(g_attn + ab + (size_t)(gn+8)*NTOK + m) = make_float2(e2, e3);
            }
        }
    }
    __syncthreads();
#pragma unroll
    for (int mi = 0; mi < 2; mi++) {
        int r = wg*64 + wr*32 + mi*16 + gid;
        atomicAdd(&ssum[r],   rs[mi][0]);
        atomicAdd(&ssum[r+8], rs[mi][1]);
    }
    __syncthreads();
    if (t < 128) g_rsinv[bh*NTOK + n0 + t] = 1.0f / ssum[t];
}

// ---------------- K4: M = (-0.5*theta) @ gnn_w ----------------
__global__ void mcompute_kernel(const float* __restrict__ theta,
                                const float* __restrict__ gw) {
    int idx = threadIdx.x;
    if (idx < NH*NH) {
        int i = idx / NH, k = idx - i*NH;
        float s = 0.f;
#pragma unroll
        for (int j = 0; j < NH; j++) s += theta[i*NH+j] * gw[j*NH+k];
        g_M[idx] = -0.5f * s;
    }
}

// ---------------- K5: in-place P = a + relu(M @ a), float4 (proven R6) ----------------
__global__ void pmix_kernel() {
    __shared__ float Ms[NH*NH];
    if (threadIdx.x < NH*NH) Ms[threadIdx.x] = g_M[threadIdx.x];
    __syncthreads();
    size_t pos4 = (size_t)blockIdx.x * 256 + threadIdx.x;
    int b   = (int)(pos4 >> 18);
    int nm4 = (int)(pos4 & (size_t)(NN/4 - 1));
    int n   = nm4 >> 8;
    size_t base = (size_t)b * NH * NN + (size_t)nm4 * 4;
    float4 a[NH];
#pragma unroll
    for (int h = 0; h < NH; h++) {
        float inv = g_rsinv[(b*NH + h)*NTOK + n];
        float4 e = *(const float4*)(g_attn + base + (size_t)h*NN);
        a[h] = make_float4(e.x*inv, e.y*inv, e.z*inv, e.w*inv);
    }
#pragma unroll
    for (int i = 0; i < NH; i++) {
        float sx = 0.f, sy = 0.f, sz = 0.f, sw = 0.f;
#pragma unroll
        for (int k = 0; k < NH; k++) {
            float m = Ms[i*NH+k];
            sx += m*a[k].x; sy += m*a[k].y; sz += m*a[k].z; sw += m*a[k].w;
        }
        float4 o = make_float4(a[i].x + fmaxf(sx, 0.f), a[i].y + fmaxf(sy, 0.f),
                               a[i].z + fmaxf(sz, 0.f), a[i].w + fmaxf(sw, 0.f));
        *(float4*)(g_attn + base + (size_t)i*NN) = o;
    }
}

// ---------------- K6: O = P @ V per bh (tf32 mma), grid (8, 24) (proven) ----------------
__global__ void pv_mma_kernel() {
    __shared__ float Ps[128][36];
    __shared__ float Vs[32][68];
    int t = threadIdx.x;
    int lane = t & 31, wid = t >> 5;
    int wr = wid >> 1, wc = wid & 1;
    int gid = lane >> 2, tig = lane & 3;
    int bh = blockIdx.y;
    int n0 = blockIdx.x * 128;
    size_t ab = (size_t)bh * NN;
    size_t vb = (size_t)bh * NTOK * DH;
    int ar = t >> 3, ac4 = t & 7;
    float acc[2][4][4] = {};
    for (int k0 = 0; k0 < NTOK; k0 += 32) {
        float4 pv[4], vv[2];
#pragma unroll
        for (int i = 0; i < 4; i++)
            pv[i] = *(const float4*)(g_attn + ab + (size_t)(n0 + ar + i*32)*NTOK + k0 + ac4*4);
#pragma unroll
        for (int i = 0; i < 2; i++) {
            int idx = i*256 + t;
            int r = idx >> 4, c4 = idx & 15;
            vv[i] = *(const float4*)(g_v + vb + (size_t)(k0+r)*DH + c4*4);
        }
        __syncthreads();
#pragma unroll
        for (int i = 0; i < 4; i++) {
            float* p = &Ps[ar + i*32][ac4*4];
            p[0]=f2t(pv[i].x); p[1]=f2t(pv[i].y); p[2]=f2t(pv[i].z); p[3]=f2t(pv[i].w);
        }
#pragma unroll
        for (int i = 0; i < 2; i++) {
            int idx = i*256 + t;
            int r = idx >> 4, c4 = idx & 15;
            float* p = &Vs[r][c4*4];
            p[0]=f2t(vv[i].x); p[1]=f2t(vv[i].y); p[2]=f2t(vv[i].z); p[3]=f2t(vv[i].w);
        }
        __syncthreads();
#pragma unroll
        for (int ks = 0; ks < 4; ks++) {
            int kk = ks*8;
            unsigned a[2][4], b[4][2];
#pragma unroll
            for (int mi = 0; mi < 2; mi++) {
                int r = wr*32 + mi*16 + gid;
                a[mi][0] = fb(Ps[r][kk+tig]);     a[mi][1] = fb(Ps[r+8][kk+tig]);
                a[mi][2] = fb(Ps[r][kk+tig+4]);   a[mi][3] = fb(Ps[r+8][kk+tig+4]);
            }
#pragma unroll
            for (int nj = 0; nj < 4; nj++) {
                int cb = wc*32 + nj*8 + gid;
                b[nj][0] = fb(Vs[kk+tig][cb]);    b[nj][1] = fb(Vs[kk+tig+4][cb]);
            }
#pragma unroll
            for (int mi = 0; mi < 2; mi++)
#pragma unroll
                for (int nj = 0; nj < 4; nj++)
                    mma_tf32(acc[mi][nj], a[mi], b[nj]);
        }
    }
#pragma unroll
    for (int mi = 0; mi < 2; mi++)
#pragma unroll
        for (int nj = 0; nj < 4; nj++) {
            int n = n0 + wr*32 + mi*16 + gid;
            int d = wc*32 + nj*8 + 2*tig;
            g_o[vb + (size_t)n*DH + d]       = acc[mi][nj][0];
            g_o[vb + (size_t)n*DH + d + 1]   = acc[mi][nj][1];
            g_o[vb + (size_t)(n+8)*DH + d]   = acc[mi][nj][2];
            g_o[vb + (size_t)(n+8)*DH + d+1] = acc[mi][nj][3];
        }
}

// ---------------- K7: Y = gather(O) @ w_out^T + b_out (tf32 mma, proven) ----------------
__global__ void oproj_mma_kernel(const float* __restrict__ wout,
                                 const float* __restrict__ bout,
                                 float* __restrict__ out) {
    __shared__ float As[128][36];
    __shared__ float Bs[64][36];
    int t = threadIdx.x;
    int lane = t & 31, wid = t >> 5;
    int wr = wid >> 1, wc = wid & 1;
    int gid = lane >> 2, tig = lane & 3;
    int i0 = blockIdx.y * 128, o0 = blockIdx.x * 64;
    int ar = t >> 3, ac4 = t & 7;
    float acc[2][4][4] = {};
    for (int k0 = 0; k0 < DM; k0 += 32) {
        int h = k0 >> 6;
        int dd = (k0 & 63) + ac4*4;
        float4 av[4], bv[2];
#pragma unroll
        for (int i = 0; i < 4; i++) {
            int gi = i0 + ar + i*32;
            int b_ = gi >> 10, n = gi & 1023;
            av[i] = *(const float4*)(g_o + (((size_t)b_*NH + h)*NTOK + n)*DH + dd);
        }
#pragma unroll
        for (int i = 0; i < 2; i++)
            bv[i] = *(const float4*)(wout + (size_t)(o0 + ar + i*32)*DM + k0 + ac4*4);
        __syncthreads();
#pragma unroll
        for (int i = 0; i < 4; i++) {
            float* p = &As[ar + i*32][ac4*4];
            p[0]=f2t(av[i].x); p[1]=f2t(av[i].y); p[2]=f2t(av[i].z); p[3]=f2t(av[i].w);
        }
#pragma unroll
        for (int i = 0; i < 2; i++) {
            float* p = &Bs[ar + i*32][ac4*4];
            p[0]=f2t(bv[i].x); p[1]=f2t(bv[i].y); p[2]=f2t(bv[i].z); p[3]=f2t(bv[i].w);
        }
        __syncthreads();
#pragma unroll
        for (int ks = 0; ks < 4; ks++) {
            int kk = ks*8;
            unsigned a[2][4], b[4][2];
#pragma unroll
            for (int mi = 0; mi < 2; mi++) {
                int r = wr*32 + mi*16 + gid;
                a[mi][0] = fb(As[r][kk+tig]);     a[mi][1] = fb(As[r+8][kk+tig]);
                a[mi][2] = fb(As[r][kk+tig+4]);   a[mi][3] = fb(As[r+8][kk+tig+4]);
            }
#pragma unroll
            for (int nj = 0; nj < 4; nj++) {
                int cb = wc*32 + nj*8 + gid;
                b[nj][0] = fb(Bs[cb][kk+tig]);    b[nj][1] = fb(Bs[cb][kk+tig+4]);
            }
#pragma unroll
            for (int mi = 0; mi < 2; mi++)
#pragma unroll
                for (int nj = 0; nj < 4; nj++)
                    mma_tf32(acc[mi][nj], a[mi], b[nj]);
        }
    }
#pragma unroll
    for (int mi = 0; mi < 2; mi++)
#pragma unroll
        for (int nj = 0; nj < 4; nj++) {
            int gi = i0 + wr*32 + mi*16 + gid;
            int o  = o0 + wc*32 + nj*8 + 2*tig;
            out[(size_t)gi*DM + o]       = acc[mi][nj][0] + bout[o];
            out[(size_t)gi*DM + o + 1]   = acc[mi][nj][1] + bout[o+1];
            out[(size_t)(gi+8)*DM + o]   = acc[mi][nj][2] + bout[o];
            out[(size_t)(gi+8)*DM + o+1] = acc[mi][nj][3] + bout[o+1];
        }
}

// ---------------- launch ----------------
extern "C" void kernel_launch(void* const* d_in, const int* in_sizes, int n_in,
                              void* d_out, int out_size) {
    const float* x      = (const float*)d_in[0];
    const float* ln_g   = (const float*)d_in[1];
    const float* ln_b   = (const float*)d_in[2];
    const float* w_qkv  = (const float*)d_in[3];
    const float* w_out  = (const float*)d_in[4];
    const float* b_out  = (const float*)d_in[5];
    const float* theta  = (const float*)d_in[6];
    const float* gnn_w  = (const float*)d_in[7];
    float* out = (float*)d_out;

    ln_kernel<<<NB*NTOK, 256>>>(x, ln_g, ln_b);
    qkv_mma_kernel<<<dim3(3*DM/128, NB*NTOK/128), 256>>>(w_qkv);      // (18,16)
    mcompute_kernel<<<1, 160>>>(theta, gnn_w);
    attn_mma_kernel<<<dim3(NTOK/128, BHH), 256>>>();                   // (8,24)
    pmix_kernel<<<(NB*NN/4)/256, 256>>>();                             // 2048
    pv_mma_kernel<<<dim3(NTOK/128, BHH), 256>>>();                     // (8,24)
    oproj_mma_kernel<<<dim3(DM/64, NB*NTOK/128), 256>>>(w_out, b_out, out); // (12,16)
}

// round 12
// speedup vs baseline: 2.3252x; 1.0090x over previous
#include <cuda_runtime.h>

#define NB    2
#define NTOK  1024
#define DM    768
#define NH    12
#define DH    64
#define BHH   (NB*NH)
#define NN    (NTOK*NTOK)
#define QK_SCALE 0.125f

// ---------------- scratch (static device memory; no allocations) ----------------
__device__ float g_xn[NB*NTOK*DM];
__device__ float g_q[BHH*NTOK*DH];
__device__ float g_k[BHH*NTOK*DH];
__device__ float g_v[BHH*NTOK*DH];
__device__ float g_o[BHH*NTOK*DH];
__device__ float g_rsum[BHH*NTOK];
__device__ float g_M[NH*NH];
__device__ float g_attn[(size_t)BHH*NN];   // ~100.7 MB

// ---------------- tf32 helpers ----------------
__device__ __forceinline__ float f2t(float x) {
    unsigned u;
    asm("cvt.rna.tf32.f32 %0, %1;" : "=r"(u) : "f"(x));
    return __uint_as_float(u);
}
__device__ __forceinline__ unsigned fb(float x) { return __float_as_uint(x); }

__device__ __forceinline__ void mma_tf32(float c[4], const unsigned a[4], const unsigned b[2]) {
    asm volatile(
        "mma.sync.aligned.m16n8k8.row.col.f32.tf32.tf32.f32 "
        "{%0,%1,%2,%3}, {%4,%5,%6,%7}, {%8,%9}, {%0,%1,%2,%3};\n"
        : "+f"(c[0]), "+f"(c[1]), "+f"(c[2]), "+f"(c[3])
        : "r"(a[0]), "r"(a[1]), "r"(a[2]), "r"(a[3]), "r"(b[0]), "r"(b[1]));
}

// ---------------- K0: zero the rowsum accumulator ----------------
__global__ void zero_rsum_kernel() {
    g_rsum[blockIdx.x * 1024 + threadIdx.x] = 0.f;
}

// ---------------- K1: LayerNorm (proven) ----------------
__global__ void ln_kernel(const float* __restrict__ x,
                          const float* __restrict__ gamma,
                          const float* __restrict__ beta) {
    int row = blockIdx.x;
    const float* xr = x + (size_t)row * DM;
    int t = threadIdx.x;
    float v[3];
    float s = 0.f, ss = 0.f;
#pragma unroll
    for (int i = 0; i < 3; i++) {
        v[i] = xr[t + i*256];
        s += v[i]; ss += v[i]*v[i];
    }
#pragma unroll
    for (int o = 16; o > 0; o >>= 1) {
        s  += __shfl_xor_sync(0xffffffffu, s,  o);
        ss += __shfl_xor_sync(0xffffffffu, ss, o);
    }
    __shared__ float sm1[8], sm2[8];
    int lane = t & 31, w = t >> 5;
    if (lane == 0) { sm1[w] = s; sm2[w] = ss; }
    __syncthreads();
    if (t == 0) {
        float a = 0.f, b = 0.f;
#pragma unroll
        for (int i = 0; i < 8; i++) { a += sm1[i]; b += sm2[i]; }
        sm1[0] = a; sm2[0] = b;
    }
    __syncthreads();
    float mean = sm1[0] * (1.f/DM);
    float var  = sm2[0] * (1.f/DM) - mean*mean;
    float inv  = rsqrtf(var + 1e-5f);
    float* outr = g_xn + (size_t)row * DM;
#pragma unroll
    for (int i = 0; i < 3; i++) {
        int c = t + i*256;
        outr[c] = (v[i]-mean)*inv*gamma[c] + beta[c];
    }
}

// ---------------- K2: QKV GEMM (tf32 mma)  C[2048,2304] = xn @ w_qkv^T (proven R6) ----------------
__device__ __forceinline__ void qkv_store(int gi, int gj, float v) {
    int b = gi >> 10, n = gi & 1023;
    int which = gj / DM;
    int r = gj - which*DM;
    int h = r >> 6, d = r & 63;
    float* dst = (which == 0) ? g_q : (which == 1 ? g_k : g_v);
    dst[(((size_t)b*NH + h)*NTOK + n)*DH + d] = v;
}

__global__ void qkv_mma_kernel(const float* __restrict__ wqkv) {
    __shared__ float As[128][36];
    __shared__ float Bs[128][36];
    int t = threadIdx.x;
    int lane = t & 31, wid = t >> 5;
    int wr = wid >> 1, wc = wid & 1;
    int gid = lane >> 2, tig = lane & 3;
    int i0 = blockIdx.y * 128, j0 = blockIdx.x * 128;
    int ar = t >> 3, ac4 = t & 7;
    float acc[2][8][4] = {};
    for (int k0 = 0; k0 < DM; k0 += 32) {
        float4 av[4], bv[4];
#pragma unroll
        for (int i = 0; i < 4; i++)
            av[i] = *(const float4*)(g_xn + (size_t)(i0 + ar + i*32)*DM + k0 + ac4*4);
#pragma unroll
        for (int i = 0; i < 4; i++)
            bv[i] = *(const float4*)(wqkv + (size_t)(j0 + ar + i*32)*DM + k0 + ac4*4);
        __syncthreads();
#pragma unroll
        for (int i = 0; i < 4; i++) {
            float* p = &As[ar + i*32][ac4*4];
            p[0]=f2t(av[i].x); p[1]=f2t(av[i].y); p[2]=f2t(av[i].z); p[3]=f2t(av[i].w);
        }
#pragma unroll
        for (int i = 0; i < 4; i++) {
            float* p = &Bs[ar + i*32][ac4*4];
            p[0]=f2t(bv[i].x); p[1]=f2t(bv[i].y); p[2]=f2t(bv[i].z); p[3]=f2t(bv[i].w);
        }
        __syncthreads();
#pragma unroll
        for (int ks = 0; ks < 4; ks++) {
            int kk = ks*8;
            unsigned a[2][4], b[8][2];
#pragma unroll
            for (int mi = 0; mi < 2; mi++) {
                int r = wr*32 + mi*16 + gid;
                a[mi][0] = fb(As[r][kk+tig]);     a[mi][1] = fb(As[r+8][kk+tig]);
                a[mi][2] = fb(As[r][kk+tig+4]);   a[mi][3] = fb(As[r+8][kk+tig+4]);
            }
#pragma unroll
            for (int nj = 0; nj < 8; nj++) {
                int cb = wc*64 + nj*8 + gid;
                b[nj][0] = fb(Bs[cb][kk+tig]);    b[nj][1] = fb(Bs[cb][kk+tig+4]);
            }
#pragma unroll
            for (int mi = 0; mi < 2; mi++)
#pragma unroll
                for (int nj = 0; nj < 8; nj++)
                    mma_tf32(acc[mi][nj], a[mi], b[nj]);
        }
    }
#pragma unroll
    for (int mi = 0; mi < 2; mi++)
#pragma unroll
        for (int nj = 0; nj < 8; nj++) {
            int gi = i0 + wr*32 + mi*16 + gid;
            int gj = j0 + wc*64 + nj*8 + 2*tig;
            qkv_store(gi,     gj,     acc[mi][nj][0]);
            qkv_store(gi,     gj + 1, acc[mi][nj][1]);
            qkv_store(gi + 8, gj,     acc[mi][nj][2]);
            qkv_store(gi + 8, gj + 1, acc[mi][nj][3]);
        }
}

// ---------------- K3: attn v4 (tf32 mma), m-split x2 ----------------
// grid (NTOK/128, BHH, 2), 256 thr = 2 groups x 4 warps; each block does 512 m-cols.
// Partial row sums atomically accumulated into g_rsum.
__global__ void attn_mma_kernel() {
    __shared__ float Ks[64][68];     // phase 1: Q staging; main loop: K tile
    __shared__ float ssum[128];
    int t = threadIdx.x;
    int lane = t & 31, wid = t >> 5;
    int wg = wid >> 2;
    int wl = wid & 3;
    int wr = wl >> 1, wc = wl & 1;
    int gid = lane >> 2, tig = lane & 3;
    int bh = blockIdx.y;
    int n0 = blockIdx.x * 128;
    int mbeg = blockIdx.z * (NTOK/2);
    size_t qb = (size_t)bh * NTOK * DH;
    size_t ab = (size_t)bh * NN;

    if (t < 128) ssum[t] = 0.f;

    // two-phase Q fragment hoist through the shared buffer
    unsigned qf[2][8][4];
#pragma unroll
    for (int g = 0; g < 2; g++) {
        __syncthreads();
#pragma unroll
        for (int i = 0; i < 4; i++) {
            int idx = i*256 + t;
            int r = idx >> 4, c4 = idx & 15;
            float4 q4 = *(const float4*)(g_q + qb + (size_t)(n0 + g*64 + r)*DH + c4*4);
            float* p = &Ks[r][c4*4];
            p[0]=f2t(q4.x); p[1]=f2t(q4.y); p[2]=f2t(q4.z); p[3]=f2t(q4.w);
        }
        __syncthreads();
        if (wg == g) {
#pragma unroll
            for (int mi = 0; mi < 2; mi++) {
                int r = wr*32 + mi*16 + gid;
#pragma unroll
                for (int ks = 0; ks < 8; ks++) {
                    int kk = ks*8;
                    qf[mi][ks][0] = fb(Ks[r][kk+tig]);     qf[mi][ks][1] = fb(Ks[r+8][kk+tig]);
                    qf[mi][ks][2] = fb(Ks[r][kk+tig+4]);   qf[mi][ks][3] = fb(Ks[r+8][kk+tig+4]);
                }
            }
        }
    }

    float rs[2][2] = {};
    for (int m0 = mbeg; m0 < mbeg + NTOK/2; m0 += 64) {
        float4 kv[4];
#pragma unroll
        for (int i = 0; i < 4; i++) {
            int idx = i*256 + t;
            int r = idx >> 4, c4 = idx & 15;
            kv[i] = *(const float4*)(g_k + qb + (size_t)(m0+r)*DH + c4*4);
        }
        __syncthreads();
#pragma unroll
        for (int i = 0; i < 4; i++) {
            int idx = i*256 + t;
            int r = idx >> 4, c4 = idx & 15;
            float* p = &Ks[r][c4*4];
            p[0]=f2t(kv[i].x); p[1]=f2t(kv[i].y); p[2]=f2t(kv[i].z); p[3]=f2t(kv[i].w);
        }
        __syncthreads();
        float acc[2][4][4] = {};
#pragma unroll
        for (int ks = 0; ks < 8; ks++) {
            int kk = ks*8;
            unsigned b[4][2];
#pragma unroll
            for (int nj = 0; nj < 4; nj++) {
                int cb = wc*32 + nj*8 + gid;
                b[nj][0] = fb(Ks[cb][kk+tig]);  b[nj][1] = fb(Ks[cb][kk+tig+4]);
            }
#pragma unroll
            for (int mi = 0; mi < 2; mi++)
#pragma unroll
                for (int nj = 0; nj < 4; nj++)
                    mma_tf32(acc[mi][nj], qf[mi][ks], b[nj]);
        }
#pragma unroll
        for (int mi = 0; mi < 2; mi++) {
            int gn = n0 + wg*64 + wr*32 + mi*16 + gid;
#pragma unroll
            for (int nj = 0; nj < 4; nj++) {
                int m = m0 + wc*32 + nj*8 + 2*tig;
                float e0 = __expf(acc[mi][nj][0]*QK_SCALE);
                float e1 = __expf(acc[mi][nj][1]*QK_SCALE);
                float e2 = __expf(acc[mi][nj][2]*QK_SCALE);
                float e3 = __expf(acc[mi][nj][3]*QK_SCALE);
                rs[mi][0] += e0 + e1;
                rs[mi][1] += e2 + e3;
                *(float2*)(g_attn + ab + (size_t)gn*NTOK + m)     = make_float2(e0, e1);
                *(float2*)(g_attn + ab + (size_t)(gn+8)*NTOK + m) = make_float2(e2, e3);
            }
        }
    }
    __syncthreads();
#pragma unroll
    for (int mi = 0; mi < 2; mi++) {
        int r = wg*64 + wr*32 + mi*16 + gid;
        atomicAdd(&ssum[r],   rs[mi][0]);
        atomicAdd(&ssum[r+8], rs[mi][1]);
    }
    __syncthreads();
    if (t < 128) atomicAdd(&g_rsum[bh*NTOK + n0 + t], ssum[t]);
}

// ---------------- K4: M = (-0.5*theta) @ gnn_w ----------------
__global__ void mcompute_kernel(const float* __restrict__ theta,
                                const float* __restrict__ gw) {
    int idx = threadIdx.x;
    if (idx < NH*NH) {
        int i = idx / NH, k = idx - i*NH;
        float s = 0.f;
#pragma unroll
        for (int j = 0; j < NH; j++) s += theta[i*NH+j] * gw[j*NH+k];
        g_M[idx] = -0.5f * s;
    }
}

// ---------------- K5: in-place P = a + relu(M @ a), float4; divides by g_rsum ----------------
__global__ void pmix_kernel() {
    __shared__ float Ms[NH*NH];
    if (threadIdx.x < NH*NH) Ms[threadIdx.x] = g_M[threadIdx.x];
    __syncthreads();
    size_t pos4 = (size_t)blockIdx.x * 256 + threadIdx.x;
    int b   = (int)(pos4 >> 18);
    int nm4 = (int)(pos4 & (size_t)(NN/4 - 1));
    int n   = nm4 >> 8;
    size_t base = (size_t)b * NH * NN + (size_t)nm4 * 4;
    float4 a[NH];
#pragma unroll
    for (int h = 0; h < NH; h++) {
        float inv = 1.0f / g_rsum[(b*NH + h)*NTOK + n];
        float4 e = *(const float4*)(g_attn + base + (size_t)h*NN);
        a[h] = make_float4(e.x*inv, e.y*inv, e.z*inv, e.w*inv);
    }
#pragma unroll
    for (int i = 0; i < NH; i++) {
        float sx = 0.f, sy = 0.f, sz = 0.f, sw = 0.f;
#pragma unroll
        for (int k = 0; k < NH; k++) {
            float m = Ms[i*NH+k];
            sx += m*a[k].x; sy += m*a[k].y; sz += m*a[k].z; sw += m*a[k].w;
        }
        float4 o = make_float4(a[i].x + fmaxf(sx, 0.f), a[i].y + fmaxf(sy, 0.f),
                               a[i].z + fmaxf(sz, 0.f), a[i].w + fmaxf(sw, 0.f));
        *(float4*)(g_attn + base + (size_t)i*NN) = o;
    }
}

// ---------------- K6: O = P @ V per bh (tf32 mma) v2 ----------------
// grid (NTOK/64, BHH), 128 thr = 4 warps (2x2), block 64n x 64d, warp 32x32, k-chunk 32.
__global__ void pv_mma_kernel() {
    __shared__ float Ps[64][36];
    __shared__ float Vs[32][68];
    int t = threadIdx.x;
    int lane = t & 31, wid = t >> 5;
    int wr = wid >> 1, wc = wid & 1;
    int gid = lane >> 2, tig = lane & 3;
    int bh = blockIdx.y;
    int n0 = blockIdx.x * 64;
    size_t ab = (size_t)bh * NN;
    size_t vb = (size_t)bh * NTOK * DH;
    float acc[2][4][4] = {};
    for (int k0 = 0; k0 < NTOK; k0 += 32) {
        float4 pv[4], vv[4];
#pragma unroll
        for (int i = 0; i < 4; i++) {
            int idx = i*128 + t;             // 512 float4s of P tile (64 x 32)
            int r = idx >> 3, c4 = idx & 7;
            pv[i] = *(const float4*)(g_attn + ab + (size_t)(n0+r)*NTOK + k0 + c4*4);
        }
#pragma unroll
        for (int i = 0; i < 4; i++) {
            int idx = i*128 + t;             // 512 float4s of V tile (32 x 64)
            int r = idx >> 4, c4 = idx & 15;
            vv[i] = *(const float4*)(g_v + vb + (size_t)(k0+r)*DH + c4*4);
        }
        __syncthreads();
#pragma unroll
        for (int i = 0; i < 4; i++) {
            int idx = i*128 + t;
            int r = idx >> 3, c4 = idx & 7;
            float* p = &Ps[r][c4*4];
            p[0]=f2t(pv[i].x); p[1]=f2t(pv[i].y); p[2]=f2t(pv[i].z); p[3]=f2t(pv[i].w);
        }
#pragma unroll
        for (int i = 0; i < 4; i++) {
            int idx = i*128 + t;
            int r = idx >> 4, c4 = idx & 15;
            float* p = &Vs[r][c4*4];
            p[0]=f2t(vv[i].x); p[1]=f2t(vv[i].y); p[2]=f2t(vv[i].z); p[3]=f2t(vv[i].w);
        }
        __syncthreads();
#pragma unroll
        for (int ks = 0; ks < 4; ks++) {
            int kk = ks*8;
            unsigned a[2][4], b[4][2];
#pragma unroll
            for (int mi = 0; mi < 2; mi++) {
                int r = wr*32 + mi*16 + gid;
                a[mi][0] = fb(Ps[r][kk+tig]);     a[mi][1] = fb(Ps[r+8][kk+tig]);
                a[mi][2] = fb(Ps[r][kk+tig+4]);   a[mi][3] = fb(Ps[r+8][kk+tig+4]);
            }
#pragma unroll
            for (int nj = 0; nj < 4; nj++) {
                int cb = wc*32 + nj*8 + gid;
                b[nj][0] = fb(Vs[kk+tig][cb]);    b[nj][1] = fb(Vs[kk+tig+4][cb]);
            }
#pragma unroll
            for (int mi = 0; mi < 2; mi++)
#pragma unroll
                for (int nj = 0; nj < 4; nj++)
                    mma_tf32(acc[mi][nj], a[mi], b[nj]);
        }
    }
#pragma unroll
    for (int mi = 0; mi < 2; mi++)
#pragma unroll
        for (int nj = 0; nj < 4; nj++) {
            int n = n0 + wr*32 + mi*16 + gid;
            int d = wc*32 + nj*8 + 2*tig;
            g_o[vb + (size_t)n*DH + d]       = acc[mi][nj][0];
            g_o[vb + (size_t)n*DH + d + 1]   = acc[mi][nj][1];
            g_o[vb + (size_t)(n+8)*DH + d]   = acc[mi][nj][2];
            g_o[vb + (size_t)(n+8)*DH + d+1] = acc[mi][nj][3];
        }
}

// ---------------- K7: Y = gather(O) @ w_out^T + b_out (tf32 mma, proven) ----------------
__global__ void oproj_mma_kernel(const float* __restrict__ wout,
                                 const float* __restrict__ bout,
                                 float* __restrict__ out) {
    __shared__ float As[128][36];
    __shared__ float Bs[64][36];
    int t = threadIdx.x;
    int lane = t & 31, wid = t >> 5;
    int wr = wid >> 1, wc = wid & 1;
    int gid = lane >> 2, tig = lane & 3;
    int i0 = blockIdx.y * 128, o0 = blockIdx.x * 64;
    int ar = t >> 3, ac4 = t & 7;
    float acc[2][4][4] = {};
    for (int k0 = 0; k0 < DM; k0 += 32) {
        int h = k0 >> 6;
        int dd = (k0 & 63) + ac4*4;
        float4 av[4], bv[2];
#pragma unroll
        for (int i = 0; i < 4; i++) {
            int gi = i0 + ar + i*32;
            int b_ = gi >> 10, n = gi & 1023;
            av[i] = *(const float4*)(g_o + (((size_t)b_*NH + h)*NTOK + n)*DH + dd);
        }
#pragma unroll
        for (int i = 0; i < 2; i++)
            bv[i] = *(const float4*)(wout + (size_t)(o0 + ar + i*32)*DM + k0 + ac4*4);
        __syncthreads();
#pragma unroll
        for (int i = 0; i < 4; i++) {
            float* p = &As[ar + i*32][ac4*4];
            p[0]=f2t(av[i].x); p[1]=f2t(av[i].y); p[2]=f2t(av[i].z); p[3]=f2t(av[i].w);
        }
#pragma unroll
        for (int i = 0; i < 2; i++) {
            float* p = &Bs[ar + i*32][ac4*4];
            p[0]=f2t(bv[i].x); p[1]=f2t(bv[i].y); p[2]=f2t(bv[i].z); p[3]=f2t(bv[i].w);
        }
        __syncthreads();
#pragma unroll
        for (int ks = 0; ks < 4; ks++) {
            int kk = ks*8;
            unsigned a[2][4], b[4][2];
#pragma unroll
            for (int mi = 0; mi < 2; mi++) {
                int r = wr*32 + mi*16 + gid;
                a[mi][0] = fb(As[r][kk+tig]);     a[mi][1] = fb(As[r+8][kk+tig]);
                a[mi][2] = fb(As[r][kk+tig+4]);   a[mi][3] = fb(As[r+8][kk+tig+4]);
            }
#pragma unroll
            for (int nj = 0; nj < 4; nj++) {
                int cb = wc*32 + nj*8 + gid;
                b[nj][0] = fb(Bs[cb][kk+tig]);    b[nj][1] = fb(Bs[cb][kk+tig+4]);
            }
#pragma unroll
            for (int mi = 0; mi < 2; mi++)
#pragma unroll
                for (int nj = 0; nj < 4; nj++)
                    mma_tf32(acc[mi][nj], a[mi], b[nj]);
        }
    }
#pragma unroll
    for (int mi = 0; mi < 2; mi++)
#pragma unroll
        for (int nj = 0; nj < 4; nj++) {
            int gi = i0 + wr*32 + mi*16 + gid;
            int o  = o0 + wc*32 + nj*8 + 2*tig;
            out[(size_t)gi*DM + o]       = acc[mi][nj][0] + bout[o];
            out[(size_t)gi*DM + o + 1]   = acc[mi][nj][1] + bout[o+1];
            out[(size_t)(gi+8)*DM + o]   = acc[mi][nj][2] + bout[o];
            out[(size_t)(gi+8)*DM + o+1] = acc[mi][nj][3] + bout[o+1];
        }
}

// ---------------- launch ----------------
extern "C" void kernel_launch(void* const* d_in, const int* in_sizes, int n_in,
                              void* d_out, int out_size) {
    const float* x      = (const float*)d_in[0];
    const float* ln_g   = (const float*)d_in[1];
    const float* ln_b   = (const float*)d_in[2];
    const float* w_qkv  = (const float*)d_in[3];
    const float* w_out  = (const float*)d_in[4];
    const float* b_out  = (const float*)d_in[5];
    const float* theta  = (const float*)d_in[6];
    const float* gnn_w  = (const float*)d_in[7];
    float* out = (float*)d_out;

    zero_rsum_kernel<<<BHH*NTOK/1024, 1024>>>();
    ln_kernel<<<NB*NTOK, 256>>>(x, ln_g, ln_b);
    qkv_mma_kernel<<<dim3(3*DM/128, NB*NTOK/128), 256>>>(w_qkv);      // (18,16)
    mcompute_kernel<<<1, 160>>>(theta, gnn_w);
    attn_mma_kernel<<<dim3(NTOK/128, BHH, 2), 256>>>();                // (8,24,2)
    pmix_kernel<<<(NB*NN/4)/256, 256>>>();                             // 2048
    pv_mma_kernel<<<dim3(NTOK/64, BHH), 128>>>();                      // (16,24)
    oproj_mma_kernel<<<dim3(DM/64, NB*NTOK/128), 256>>>(w_out, b_out, out); // (12,16)
}